// round 11
// baseline (speedup 1.0000x reference)
#include <cuda_runtime.h>
#include <cuda_fp16.h>
#include <math.h>

// ---------------- problem constants ----------------
#define BB   32
#define TT   12
#define NN   512
#define HID  64
#define EMB  10
#define BN   (BB*NN)     // 16384

// Feature K layout for the weight GEMM (208 rows):
//  0..63   X (h or z*h) | 64..127 S@X | 128..191 2S^2X-X
//  192..197 [x0,x1,Sx0,Sx1,S2x0,S2x1] | 198..207 zero pad

// ---------------- dynamic smem layout (bytes) ----------------
#define TILEH   3072        // halves per 128x24 tile
#define TILEB   6144
#define OFF_PAN 0           // 13 tiles       -> 79872
#define OFF_SS  79872       // 3 stages S     -> 18432
#define OFF_S2  98304       // 3 stages S2    -> 18432
#define OFF_XB  116736      // 3 stages 64x24 -> 9216
#define OFF_GO  125952      // 512 floats     -> 2048
#define SM_BYTES 128000

// ---------------- device scratch ----------------
__device__ float  g_h[BN*HID];
__device__ float  g_r[BN*HID];
__device__ __half g_x0 [BN*64];          // h, row-major
__device__ __half g_x0T[BB*64*NN];       // h, [b][c][n]
__device__ __half g_x1 [BN*64];          // z*h, row-major
__device__ __half g_x1T[BB*64*NN];
__device__ float  g_sup_en_f[NN*NN];
__device__ __half g_sup_en_h[NN*NN];
__device__ float  g_sup_de_f[(size_t)BB*NN*NN];
__device__ __half g_sup_de_h[(size_t)BB*NN*NN];
__device__ float  g_s2_en_f[NN*NN];
__device__ __half g_s2_en_h[NN*NN];
__device__ float  g_s2_de_f[(size_t)BB*NN*NN];
__device__ __half g_s2_de_h[(size_t)BB*NN*NN];
__device__ float  g_ne[BN*EMB];
__device__ float  g_go[BN];
__device__ float  g_xf1[BN*24];
__device__ float  g_xf2[BN*24];
__device__ float  g_yf1[BN*TT];
__device__ float  g_yf2[BN*TT];
// transposed fp16 weights: [n][208]
__device__ __half g_WgeT[128*208];
__device__ __half g_WgdT[128*208];
__device__ __half g_WueT[64*208];
__device__ __half g_WudT[64*208];

__device__ __forceinline__ int wmap(int c) {
    if (c < 64)  return c + 2;
    if (c < 128) return c + 4;
    if (c < 192) return c + 6;
    return ((c - 192) >> 1) * 66 + (c & 1);
}

// ---------------- mma helpers ----------------
__device__ __forceinline__ unsigned f2tf(float f) {
    unsigned u;
    asm("cvt.rna.tf32.f32 %0, %1;" : "=r"(u) : "f"(f));
    return u;
}
__device__ __forceinline__ void mma_tf32(float* d,
    unsigned a0, unsigned a1, unsigned a2, unsigned a3,
    unsigned b0, unsigned b1) {
    asm volatile(
        "mma.sync.aligned.m16n8k8.row.col.f32.tf32.tf32.f32 "
        "{%0,%1,%2,%3}, {%4,%5,%6,%7}, {%8,%9}, {%0,%1,%2,%3};\n"
        : "+f"(d[0]), "+f"(d[1]), "+f"(d[2]), "+f"(d[3])
        : "r"(a0), "r"(a1), "r"(a2), "r"(a3), "r"(b0), "r"(b1));
}
__device__ __forceinline__ void mma_f16(float* d,
    unsigned a0, unsigned a1, unsigned a2, unsigned a3,
    unsigned b0, unsigned b1) {
    asm volatile(
        "mma.sync.aligned.m16n8k16.row.col.f32.f16.f16.f32 "
        "{%0,%1,%2,%3}, {%4,%5,%6,%7}, {%8,%9}, {%0,%1,%2,%3};\n"
        : "+f"(d[0]), "+f"(d[1]), "+f"(d[2]), "+f"(d[3])
        : "r"(a0), "r"(a1), "r"(a2), "r"(a3), "r"(b0), "r"(b1));
}
__device__ __forceinline__ void ldsm_x4(unsigned& r0, unsigned& r1,
                                        unsigned& r2, unsigned& r3, unsigned addr) {
    asm volatile("ldmatrix.sync.aligned.m8n8.x4.shared.b16 {%0,%1,%2,%3}, [%4];"
        : "=r"(r0), "=r"(r1), "=r"(r2), "=r"(r3) : "r"(addr));
}

__device__ __forceinline__ void cpa16(void* smem, const void* g) {
    unsigned s = (unsigned)__cvta_generic_to_shared(smem);
    asm volatile("cp.async.cg.shared.global [%0], [%1], 16;\n" :: "r"(s), "l"(g));
}
#define CP_COMMIT() asm volatile("cp.async.commit_group;\n" ::: "memory")
#define CP_WAIT1()  asm volatile("cp.async.wait_group 1;\n" ::: "memory")
#define CP_WAIT0()  asm volatile("cp.async.wait_group 0;\n" ::: "memory")

// ---------------- init ----------------
__global__ void k_zero() {
    size_t i = (size_t)blockIdx.x*blockDim.x + threadIdx.x;
    size_t st = (size_t)gridDim.x*blockDim.x;
    const __half hz = __float2half(0.f);
    for (size_t j=i; j<(size_t)BN*64; j+=st) { g_x0[j] = hz; g_x0T[j] = hz; }
    for (size_t j=i; j<BN*HID; j+=st) g_h[j]  = 0.f;
    for (size_t j=i; j<BN;     j+=st) g_go[j] = 0.f;
}

// ---------------- weight reorder (transposed fp16) --------------------------
__global__ void k_prep(const float* __restrict__ W, int which) {
    int nc = (which < 2) ? 128 : 64;
    __half* dst = (which == 0) ? g_WgeT : (which == 1) ? g_WgdT
               : (which == 2) ? g_WueT : g_WudT;
    int idx = blockIdx.x*blockDim.x + threadIdx.x;
    if (idx >= 208*nc) return;
    int c = idx / nc, o = idx - c*nc;
    float v = 0.f;
    if (c < 198) v = W[wmap(c)*nc + o];
    dst[(size_t)o*208 + c] = __float2half(v);
}

// ---------------- supports (fp32 + fp16 copies) ----------------
__global__ void k_support_en(const float* __restrict__ emb) {
    int n = blockIdx.x, tid = threadIdx.x;
    __shared__ float embn[EMB];
    __shared__ float row[NN];
    __shared__ float red[256];
    if (tid < EMB) embn[tid] = emb[n*EMB + tid];
    __syncthreads();
    for (int m=tid; m<NN; m+=256) {
        float s = 0.f;
        #pragma unroll
        for (int e=0; e<EMB; e++) s += embn[e]*emb[m*EMB+e];
        row[m] = fmaxf(s, 0.f);
    }
    __syncthreads();
    float lm = -1e30f;
    for (int m=tid; m<NN; m+=256) lm = fmaxf(lm, row[m]);
    red[tid]=lm; __syncthreads();
    for (int s=128;s>0;s>>=1){ if(tid<s) red[tid]=fmaxf(red[tid],red[tid+s]); __syncthreads(); }
    float mx = red[0]; __syncthreads();
    float ls = 0.f;
    for (int m=tid; m<NN; m+=256){ float e=expf(row[m]-mx); row[m]=e; ls+=e; }
    red[tid]=ls; __syncthreads();
    for (int s=128;s>0;s>>=1){ if(tid<s) red[tid]+=red[tid+s]; __syncthreads(); }
    float inv = 1.f/red[0];
    for (int m=tid; m<NN; m+=256) {
        float v = row[m]*inv;
        g_sup_en_f[n*NN+m] = v;
        g_sup_en_h[n*NN+m] = __float2half(v);
    }
}

__global__ void k_support_de() {
    int bn = blockIdx.x;
    int b = bn >> 9, n = bn & 511;
    int tid = threadIdx.x;
    const float* neb = g_ne + (size_t)b*NN*EMB;
    __shared__ float embn[EMB];
    __shared__ float row[NN];
    __shared__ float red[256];
    if (tid < EMB) embn[tid] = neb[n*EMB + tid];
    __syncthreads();
    for (int m=tid; m<NN; m+=256) {
        float s = 0.f;
        #pragma unroll
        for (int e=0; e<EMB; e++) s += embn[e]*neb[m*EMB+e];
        row[m] = fmaxf(s, 0.f);
    }
    __syncthreads();
    float lm = -1e30f;
    for (int m=tid; m<NN; m+=256) lm = fmaxf(lm, row[m]);
    red[tid]=lm; __syncthreads();
    for (int s=128;s>0;s>>=1){ if(tid<s) red[tid]=fmaxf(red[tid],red[tid+s]); __syncthreads(); }
    float mx = red[0]; __syncthreads();
    float ls = 0.f;
    for (int m=tid; m<NN; m+=256){ float e=expf(row[m]-mx); row[m]=e; ls+=e; }
    red[tid]=ls; __syncthreads();
    for (int s=128;s>0;s>>=1){ if(tid<s) red[tid]+=red[tid+s]; __syncthreads(); }
    float inv = 1.f/red[0];
    size_t base = (size_t)b*NN*NN + (size_t)n*NN;
    for (int m=tid; m<NN; m+=256) {
        float v = row[m]*inv;
        g_sup_de_f[base+m] = v;
        g_sup_de_h[base+m] = __float2half(v);
    }
}

// ---------------- S2 = S @ S  (tf32 MMA on fp32 S; dual-format output) ------
__global__ void __launch_bounds__(256) k_sq(int deFlag) {
    __shared__ float As[3][128*20];
    __shared__ float Bs[3][16*72];
    const int b  = blockIdx.z;
    const int m0 = blockIdx.x*128;
    const int n0 = blockIdx.y*64;
    const int tid = threadIdx.x;
    const int warp = tid >> 5, lane = tid & 31;
    const int mw = warp & 3, nw = warp >> 2;
    const int tq = lane >> 2, tr = lane & 3;
    const float* S = deFlag ? g_sup_de_f + (size_t)b*NN*NN : g_sup_en_f;
    float*  Df = deFlag ? g_s2_de_f + (size_t)b*NN*NN : g_s2_en_f;
    __half* Dh = deFlag ? g_s2_de_h + (size_t)b*NN*NN : g_s2_en_h;
    const int lr = tid >> 1, lc = (tid & 1)*8;
    const int bk = tid >> 4, bn = (tid & 15)*4;

    float acc[2][4][4] = {};

#define SQ_LOAD(st, k0) do { \
    cpa16(&As[st][lr*20+lc],   &S[(size_t)(m0+lr)*NN + (k0)+lc]); \
    cpa16(&As[st][lr*20+lc+4], &S[(size_t)(m0+lr)*NN + (k0)+lc+4]); \
    cpa16(&Bs[st][bk*72+bn],   &S[(size_t)((k0)+bk)*NN + n0 + bn]); \
} while(0)

    SQ_LOAD(0, 0);  CP_COMMIT();
    SQ_LOAD(1, 16); CP_COMMIT();
    for (int kt = 0; kt < 32; kt++) {
        CP_WAIT1();
        __syncthreads();
        if (kt < 30) SQ_LOAD((kt+2)%3, (kt+2)*16);
        CP_COMMIT();
        const float* Ab = As[kt%3];
        const float* Bb = Bs[kt%3];
        #pragma unroll
        for (int ks = 0; ks < 16; ks += 8) {
            unsigned a[2][4], bb[4][2];
            #pragma unroll
            for (int mi = 0; mi < 2; mi++) {
                int r = mw*32 + mi*16 + tq;
                a[mi][0] = f2tf(Ab[r*20 + ks + tr]);
                a[mi][1] = f2tf(Ab[(r+8)*20 + ks + tr]);
                a[mi][2] = f2tf(Ab[r*20 + ks + tr + 4]);
                a[mi][3] = f2tf(Ab[(r+8)*20 + ks + tr + 4]);
            }
            #pragma unroll
            for (int nj = 0; nj < 4; nj++) {
                int c = nw*32 + nj*8 + tq;
                bb[nj][0] = f2tf(Bb[(ks+tr)*72 + c]);
                bb[nj][1] = f2tf(Bb[(ks+tr+4)*72 + c]);
            }
            #pragma unroll
            for (int mi = 0; mi < 2; mi++)
                #pragma unroll
                for (int nj = 0; nj < 4; nj++)
                    mma_tf32(acc[mi][nj], a[mi][0], a[mi][1], a[mi][2], a[mi][3],
                             bb[nj][0], bb[nj][1]);
        }
    }
    __syncthreads();
    #pragma unroll
    for (int mi = 0; mi < 2; mi++) {
        int r0 = m0 + mw*32 + mi*16 + tq;
        #pragma unroll
        for (int nj = 0; nj < 4; nj++) {
            int c = n0 + nw*32 + nj*8 + tr*2;
            #pragma unroll
            for (int hh = 0; hh < 2; hh++) {
                int rr = r0 + hh*8;
                float va = acc[mi][nj][hh*2], vb = acc[mi][nj][hh*2+1];
                *(float2*)&Df[(size_t)rr*NN + c] = make_float2(va, vb);
                *(__half2*)&Dh[(size_t)rr*NN + c] = __floats2half2_rn(va, vb);
            }
        }
    }
#undef SQ_LOAD
}

// ---------------- x/ycov feature precompute ---------------------------------
__global__ void __launch_bounds__(256) k_pre_enc(const float* __restrict__ x) {
    __shared__ float xsh[512*24];
    int b = blockIdx.y, m0 = blockIdx.x*32, z = blockIdx.z;
    int tid = threadIdx.x;
    for (int idx = tid; idx < 512*24; idx += 256) {
        int k = idx/24, tc = idx%24;
        int t = tc>>1, c = tc&1;
        xsh[idx] = x[(((size_t)b*TT+t)*NN + k)*2 + c];
    }
    __syncthreads();
    int rl = tid>>3, kh = (tid>>2)&1, cg = tid&3;
    int row = m0 + rl, g = cg*6;
    float acc[6] = {};
    const float* Srow = (z ? g_s2_en_f : g_sup_en_f) + (size_t)row*NN + kh*256;
    const float* xp = &xsh[kh*256*24];
    for (int k=0;k<256;k+=4){
        float4 s = *(const float4*)&Srow[k];
        #pragma unroll
        for (int j=0;j<6;j++)
            acc[j] += s.x*xp[(k+0)*24+g+j] + s.y*xp[(k+1)*24+g+j]
                    + s.z*xp[(k+2)*24+g+j] + s.w*xp[(k+3)*24+g+j];
    }
    #pragma unroll
    for (int j=0;j<6;j++) acc[j] += __shfl_xor_sync(0xffffffffu, acc[j], 4);
    if (kh == 0) {
        #pragma unroll
        for (int j=0;j<6;j++) {
            int col = g + j;
            if (z == 0) g_xf1[((size_t)b*NN + row)*24 + col] = acc[j];
            else {
                int t = col>>1, c = col&1;
                g_xf2[((size_t)b*NN + row)*24 + col] =
                    2.f*acc[j] - x[(((size_t)b*TT+t)*NN + row)*2 + c];
            }
        }
    }
}

__global__ void __launch_bounds__(256) k_pre_dec(const float* __restrict__ ycov) {
    __shared__ float ysh[512*12];
    int b = blockIdx.y, m0 = blockIdx.x*32, z = blockIdx.z;
    int tid = threadIdx.x;
    for (int idx = tid; idx < 512*12; idx += 256) {
        int k = idx/12, t = idx%12;
        ysh[idx] = ycov[((size_t)b*TT+t)*NN + k];
    }
    __syncthreads();
    int rl = tid>>3, kh = (tid>>2)&1, cg = tid&3;
    int row = m0 + rl, g = cg*3;
    float acc[3] = {};
    const float* Srow = (z ? g_s2_de_f : g_sup_de_f)
                        + (size_t)b*NN*NN + (size_t)row*NN + kh*256;
    const float* yp = &ysh[kh*256*12];
    for (int k=0;k<256;k+=4){
        float4 s = *(const float4*)&Srow[k];
        #pragma unroll
        for (int j=0;j<3;j++)
            acc[j] += s.x*yp[(k+0)*12+g+j] + s.y*yp[(k+1)*12+g+j]
                    + s.z*yp[(k+2)*12+g+j] + s.w*yp[(k+3)*12+g+j];
    }
    #pragma unroll
    for (int j=0;j<3;j++) acc[j] += __shfl_xor_sync(0xffffffffu, acc[j], 4);
    if (kh == 0) {
        #pragma unroll
        for (int j=0;j<3;j++) {
            int t = g + j;
            if (z == 0) g_yf1[((size_t)b*NN + row)*12 + t] = acc[j];
            else        g_yf2[((size_t)b*NN + row)*12 + t] =
                            2.f*acc[j] - ycov[((size_t)b*TT+t)*NN + row];
        }
    }
}

// ---------------- fused cell-phase kernel (512 thr, 16 warps = 8Mx2N) --------
__global__ void __launch_bounds__(512) k_cell(
    int phase, int deFlag, int t,
    const float* __restrict__ x, const float* __restrict__ ycov,
    const float* __restrict__ bias,
    const float* __restrict__ pW, const float* __restrict__ pb,
    float* __restrict__ out)
{
    extern __shared__ char smx[];
    __half* PAN = (__half*)(smx + OFF_PAN);
    __half* SS  = (__half*)(smx + OFF_SS);
    __half* S2S = (__half*)(smx + OFF_S2);
    __half* XB  = (__half*)(smx + OFF_XB);
    float*  GOs = (float*)(smx + OFF_GO);
    __shared__ float pr[2][128];

    const int b  = blockIdx.y;
    const int m0 = blockIdx.x*128;
    const int tid = threadIdx.x;
    const int warp = tid >> 5, lane = tid & 31;
    const int mw = warp & 7, nw = warp >> 3;      // 8(M) x 2(N)
    const int tq = lane >> 2, tr = lane & 3;

    // ldmatrix lane geometry
    const int l8 = lane & 7, mt = lane >> 3;
    const int arow = l8 + (mt & 1)*8;
    const int acol = (mt >> 1)*8;
    const int brow = l8 + (mt >> 1)*8;
    const int bcol = (mt & 1)*8;
    const unsigned aOff = ((mw*16 + arow)*24 + acol)*2;   // single m16 block
    const unsigned bOff0 = ((nw*32 + brow)*24 + bcol)*2;
    const unsigned bOff1 = bOff0 + 16*48;
    const unsigned uPAN = (unsigned)__cvta_generic_to_shared(PAN);
    const unsigned uSS  = (unsigned)__cvta_generic_to_shared(SS);
    const unsigned uS2  = (unsigned)__cvta_generic_to_shared(S2S);
    const unsigned uXB  = (unsigned)__cvta_generic_to_shared(XB);

    const __half* Sh  = deFlag ? g_sup_de_h + (size_t)b*NN*NN : g_sup_en_h;
    const __half* S2h = deFlag ? g_s2_de_h  + (size_t)b*NN*NN : g_s2_en_h;
    const __half* Xrow = (phase == 0) ? g_x0 : g_x1;
    const __half* XT   = (phase == 0) ? g_x0T : g_x1T;

    // ---- preload panel tiles 0..3 (X own rows): 1024 chunks, 2 per thread ---
    #pragma unroll
    for (int i = 0; i < 2; i++) {
        int ch = tid + i*512;
        int tI = ch >> 8, rw = (ch >> 1) & 127, off = (ch & 1)*8;
        cpa16(&PAN[tI*TILEH + rw*24 + off],
              &Xrow[((size_t)b*NN + m0 + rw)*64 + tI*16 + off]);
    }
    if (deFlag) GOs[tid] = g_go[(size_t)b*NN + tid];
    CP_COMMIT();

    // ---- phase A loaders ----
    const int q8  = tid & 255;
    const int lrA = q8 >> 1, loA = (q8 & 1)*8;   // S/S2 chunk
    const int xrw = tid >> 1, xlo = (tid & 1)*8; // XB chunk (tid<128)

    float acc1[4][4] = {};
    float acc2[4][4] = {};
    float d1 = 0.f, d2 = 0.f;
    const int mvrow = tid >> 2, mvh = (tid & 3)*4;

#define PA_LOAD(st, k0) do { \
    if (tid < 256) { \
        cpa16(&SS [(st)*TILEH + lrA*24 + loA], &Sh [(size_t)(m0+lrA)*NN + (k0)+loA]); \
        if (tid < 128) \
            cpa16(&XB[(st)*1536 + xrw*24 + xlo], &XT[((size_t)b*64 + xrw)*NN + (k0)+xlo]); \
    } else { \
        cpa16(&S2S[(st)*TILEH + lrA*24 + loA], &S2h[(size_t)(m0+lrA)*NN + (k0)+loA]); \
    } \
} while(0)

    PA_LOAD(0, 0);  CP_COMMIT();
    PA_LOAD(1, 16); CP_COMMIT();
    for (int kt = 0; kt < 32; kt++) {
        CP_WAIT1();
        __syncthreads();
        if (kt < 30) PA_LOAD((kt+2)%3, (kt+2)*16);
        CP_COMMIT();
        const unsigned sb  = uSS + (kt%3)*TILEB;
        const unsigned s2b = uS2 + (kt%3)*TILEB;
        const unsigned xb  = uXB + (kt%3)*3072;
        unsigned a[4], a2[4], bb[4][2];
        ldsm_x4(a [0], a [1], a [2], a [3], sb  + aOff);
        ldsm_x4(a2[0], a2[1], a2[2], a2[3], s2b + aOff);
        ldsm_x4(bb[0][0], bb[0][1], bb[1][0], bb[1][1], xb + bOff0);
        ldsm_x4(bb[2][0], bb[2][1], bb[3][0], bb[3][1], xb + bOff1);
        #pragma unroll
        for (int nj = 0; nj < 4; nj++) {
            mma_f16(acc1[nj], a [0], a [1], a [2], a [3], bb[nj][0], bb[nj][1]);
            mma_f16(acc2[nj], a2[0], a2[1], a2[2], a2[3], bb[nj][0], bb[nj][1]);
        }
        if (deFlag) {
            const __half* Ab  = SS  + (kt%3)*TILEH;
            const __half* A2b = S2S + (kt%3)*TILEH;
            const __half2* ap  = (const __half2*)&Ab [mvrow*24 + mvh];
            const __half2* a2p = (const __half2*)&A2b[mvrow*24 + mvh];
            const float* gop = &GOs[kt*16 + mvh];
            #pragma unroll
            for (int j = 0; j < 2; j++) {
                float2 v  = __half22float2(ap[j]);
                float2 v2 = __half22float2(a2p[j]);
                d1 += v.x*gop[2*j] + v.y*gop[2*j+1];
                d2 += v2.x*gop[2*j] + v2.y*gop[2*j+1];
            }
        }
    }
    CP_WAIT0();
    __syncthreads();

    // ---- write Y1 (tiles 4..7), Y2 = 2*acc2 - X (tiles 8..11) ----
    {
        int r = mw*16 + tq;
        #pragma unroll
        for (int nj = 0; nj < 4; nj++) {
            int c = nw*32 + nj*8 + tr*2;
            int tI = c >> 4, kk = c & 15;
            #pragma unroll
            for (int hh = 0; hh < 2; hh++) {
                int rr = r + hh*8;
                float v1a = acc1[nj][hh*2], v1b = acc1[nj][hh*2+1];
                float v2a = acc2[nj][hh*2], v2b = acc2[nj][hh*2+1];
                float xa  = __half2float(PAN[tI*TILEH + rr*24 + kk]);
                float xb2 = __half2float(PAN[tI*TILEH + rr*24 + kk + 1]);
                *(__half2*)&PAN[(4+tI)*TILEH + rr*24 + kk] =
                    __floats2half2_rn(v1a, v1b);
                *(__half2*)&PAN[(8+tI)*TILEH + rr*24 + kk] =
                    __floats2half2_rn(2.f*v2a - xa, 2.f*v2b - xb2);
            }
        }
    }

    // ---- tile 12: extra features ----
    if (deFlag) {
        d1 += __shfl_xor_sync(0xffffffffu, d1, 1);
        d1 += __shfl_xor_sync(0xffffffffu, d1, 2);
        d2 += __shfl_xor_sync(0xffffffffu, d2, 1);
        d2 += __shfl_xor_sync(0xffffffffu, d2, 2);
        if ((tid & 3) == 0) {
            int rw = tid >> 2;
            size_t gr = (size_t)b*NN + m0 + rw;
            float go = GOs[m0 + rw];
            __half* T = &PAN[12*TILEH + rw*24];
            T[0] = __float2half(go);
            T[1] = __float2half(ycov[((size_t)b*TT + t)*NN + m0 + rw]);
            T[2] = __float2half(d1);
            T[3] = __float2half(g_yf1[gr*12 + t]);
            T[4] = __float2half(2.f*d2 - go);
            T[5] = __float2half(g_yf2[gr*12 + t]);
            #pragma unroll
            for (int j = 6; j < 16; j++) T[j] = __float2half(0.f);
        }
    } else {
        if (tid < 128) {
            int rw = tid;
            size_t gr = (size_t)b*NN + m0 + rw;
            const float* xp = &x[(((size_t)b*TT + t)*NN + m0 + rw)*2];
            __half* T = &PAN[12*TILEH + rw*24];
            T[0] = __float2half(xp[0]);
            T[1] = __float2half(xp[1]);
            T[2] = __float2half(g_xf1[gr*24 + t*2 + 0]);
            T[3] = __float2half(g_xf1[gr*24 + t*2 + 1]);
            T[4] = __float2half(g_xf2[gr*24 + t*2 + 0]);
            T[5] = __float2half(g_xf2[gr*24 + t*2 + 1]);
            #pragma unroll
            for (int j = 6; j < 16; j++) T[j] = __float2half(0.f);
        }
    }
    __syncthreads();

    // ---- phase B: weight GEMM over K=208 from the panel ----
    if (phase == 0) {
        const __half* WT = deFlag ? g_WgdT : g_WgeT;
        float acc[8][4] = {};
        const unsigned bG0 = ((nw*64 + brow)*24 + bcol)*2;
#define WB_LOAD128(st, k0) do { \
    if (tid < 256) { int n_ = tid >> 1, of_ = (tid & 1)*8; \
        cpa16(&SS[(st)*TILEH + n_*24 + of_], &WT[(size_t)n_*208 + (k0)+of_]); } \
} while(0)
        WB_LOAD128(0, 0);  CP_COMMIT();
        WB_LOAD128(1, 16); CP_COMMIT();
        for (int kt = 0; kt < 13; kt++) {
            CP_WAIT1();
            __syncthreads();
            if (kt < 11) WB_LOAD128((kt+2)%3, (kt+2)*16);
            CP_COMMIT();
            const unsigned pb_ = uPAN + kt*TILEB;
            const unsigned wb  = uSS + (kt%3)*TILEB;
            unsigned a[4], bb[8][2];
            ldsm_x4(a[0], a[1], a[2], a[3], pb_ + aOff);
            #pragma unroll
            for (int j = 0; j < 4; j++)
                ldsm_x4(bb[2*j][0], bb[2*j][1], bb[2*j+1][0], bb[2*j+1][1],
                        wb + bG0 + j*16*48);
            #pragma unroll
            for (int nj = 0; nj < 8; nj++)
                mma_f16(acc[nj], a[0], a[1], a[2], a[3], bb[nj][0], bb[nj][1]);
        }
        // epilogue: z = sigmoid -> z*h into g_x1/g_x1T ; r into g_r
        {
            int r0 = mw*16 + tq;
            #pragma unroll
            for (int nj = 0; nj < 8; nj++) {
                int c = nw*64 + nj*8 + tr*2;
                #pragma unroll
                for (int hh = 0; hh < 2; hh++) {
                    int ln = m0 + r0 + hh*8;
                    size_t row = (size_t)b*NN + ln;
                    float va = acc[nj][hh*2], vb = acc[nj][hh*2+1];
                    float za = 1.f/(1.f + expf(-(va + bias[c])));
                    float zb = 1.f/(1.f + expf(-(vb + bias[c+1])));
                    if (c < 64) {
                        float ha = za * g_h[row*HID + c];
                        float hb = zb * g_h[row*HID + c+1];
                        *(__half2*)&g_x1[row*64 + c] = __floats2half2_rn(ha, hb);
                        g_x1T[((size_t)b*64 + c  )*NN + ln] = __float2half(ha);
                        g_x1T[((size_t)b*64 + c+1)*NN + ln] = __float2half(hb);
                    } else {
                        g_r[row*HID + (c-64)]   = za;
                        g_r[row*HID + (c-64)+1] = zb;
                    }
                }
            }
        }
#undef WB_LOAD128
    } else {
        const __half* WT = deFlag ? g_WudT : g_WueT;
        float acc[4][4] = {};
#define WB_LOAD64(st, k0) do { \
    if (tid < 128) { int n_ = tid >> 1, of_ = (tid & 1)*8; \
        cpa16(&SS[(st)*1536 + n_*24 + of_], &WT[(size_t)n_*208 + (k0)+of_]); } \
} while(0)
        WB_LOAD64(0, 0);  CP_COMMIT();
        WB_LOAD64(1, 16); CP_COMMIT();
        for (int kt = 0; kt < 13; kt++) {
            CP_WAIT1();
            __syncthreads();
            if (kt < 11) WB_LOAD64((kt+2)%3, (kt+2)*16);
            CP_COMMIT();
            const unsigned pb_ = uPAN + kt*TILEB;
            const unsigned wb  = uSS + (kt%3)*3072;
            unsigned a[4], bb[4][2];
            ldsm_x4(a[0], a[1], a[2], a[3], pb_ + aOff);
            ldsm_x4(bb[0][0], bb[0][1], bb[1][0], bb[1][1], wb + bOff0);
            ldsm_x4(bb[2][0], bb[2][1], bb[3][0], bb[3][1], wb + bOff1);
            #pragma unroll
            for (int nj = 0; nj < 4; nj++)
                mma_f16(acc[nj], a[0], a[1], a[2], a[3], bb[nj][0], bb[nj][1]);
        }
        // epilogue: h update (+ projection for decoder)
        const bool doProj = (deFlag != 0);
        float rowsum[2] = {};
        {
            int r0 = mw*16 + tq;
            #pragma unroll
            for (int nj = 0; nj < 4; nj++) {
                int c = nw*32 + nj*8 + tr*2;
                #pragma unroll
                for (int hh = 0; hh < 2; hh++) {
                    int ln = m0 + r0 + hh*8;
                    size_t row = (size_t)b*NN + ln;
                    float hn2[2];
                    #pragma unroll
                    for (int jj = 0; jj < 2; jj++) {
                        int o = c + jj;
                        float hc = tanhf(acc[nj][hh*2+jj] + bias[o]);
                        float r  = g_r[row*HID + o];
                        float h  = g_h[row*HID + o];
                        float hn = r*h + (1.f - r)*hc;
                        g_h[row*HID + o] = hn;
                        g_x0T[((size_t)b*64 + o)*NN + ln] = __float2half(hn);
                        hn2[jj] = hn;
                        if (doProj) rowsum[hh] += hn * pW[o];
                    }
                    *(__half2*)&g_x0[row*64 + c] = __floats2half2_rn(hn2[0], hn2[1]);
                }
            }
        }
        if (doProj) {
            #pragma unroll
            for (int hh = 0; hh < 2; hh++) {
                float v = rowsum[hh];
                v += __shfl_xor_sync(0xffffffffu, v, 1);
                v += __shfl_xor_sync(0xffffffffu, v, 2);
                if (tr == 0) pr[nw][mw*16 + tq + hh*8] = v;
            }
            __syncthreads();
            if (tid < 128) {
                int n = m0 + tid;
                float go = pr[0][tid] + pr[1][tid] + pb[0];
                g_go[(size_t)b*NN + n] = go;
                out[((size_t)b*TT + t)*NN + n] = go;
            }
        }
#undef WB_LOAD64
    }
#undef PA_LOAD
}

// ---------------- hyper projection ------------------------------------------
__global__ void k_hyper(const float* __restrict__ hW, const float* __restrict__ hb) {
    int idx = blockIdx.x*blockDim.x + threadIdx.x;
    if (idx >= BN*EMB) return;
    int bn = idx / EMB, e = idx % EMB;
    float s = hb[e];
    #pragma unroll
    for (int k = 0; k < HID; k++) s += g_h[(size_t)bn*HID + k] * hW[k*EMB + e];
    g_ne[idx] = s;
}

// ---------------- orchestration ---------------------------------------------
extern "C" void kernel_launch(void* const* d_in, const int* in_sizes, int n_in,
                              void* d_out, int out_size) {
    const float* x       = (const float*)d_in[0];
    const float* ycov    = (const float*)d_in[1];
    const float* emb     = (const float*)d_in[2];
    const float* enc_gW  = (const float*)d_in[3];
    const float* enc_gb  = (const float*)d_in[4];
    const float* enc_uW  = (const float*)d_in[5];
    const float* enc_ub  = (const float*)d_in[6];
    const float* dec_gW  = (const float*)d_in[7];
    const float* dec_gb  = (const float*)d_in[8];
    const float* dec_uW  = (const float*)d_in[9];
    const float* dec_ub  = (const float*)d_in[10];
    const float* proj_W  = (const float*)d_in[11];
    const float* proj_b  = (const float*)d_in[12];
    const float* hyper_W = (const float*)d_in[13];
    const float* hyper_b = (const float*)d_in[14];
    float* out = (float*)d_out;

    static int smem_set = 0;
    if (!smem_set) {
        cudaFuncSetAttribute(k_cell, cudaFuncAttributeMaxDynamicSharedMemorySize,
                             SM_BYTES);
        smem_set = 1;
    }

    dim3 gs_cell(4, BB);
    dim3 gs_sq_en(4, 8, 1);
    dim3 gs_sq_de(4, 8, BB);
    dim3 gs_pre(16, BB, 2);

    k_zero<<<1024, 256>>>();
    k_prep<<<(208*128+255)/256, 256>>>(enc_gW, 0);
    k_prep<<<(208*128+255)/256, 256>>>(dec_gW, 1);
    k_prep<<<(208*64+255)/256, 256>>>(enc_uW, 2);
    k_prep<<<(208*64+255)/256, 256>>>(dec_uW, 3);
    k_support_en<<<NN, 256>>>(emb);
    k_sq<<<gs_sq_en, 256>>>(0);
    k_pre_enc<<<gs_pre, 256>>>(x);

    for (int t = 0; t < TT; t++) {
        k_cell<<<gs_cell, 512, SM_BYTES>>>(0, 0, t, x, ycov, enc_gb,
                                           nullptr, nullptr, nullptr);
        k_cell<<<gs_cell, 512, SM_BYTES>>>(1, 0, t, x, ycov, enc_ub,
                                           nullptr, nullptr, nullptr);
    }

    k_hyper<<<(BN*EMB + 255)/256, 256>>>(hyper_W, hyper_b);
    k_support_de<<<BN, 256>>>();
    k_sq<<<gs_sq_de, 256>>>(1);
    k_pre_dec<<<gs_pre, 256>>>(ycov);

    for (int t = 0; t < TT; t++) {
        k_cell<<<gs_cell, 512, SM_BYTES>>>(0, 1, t, x, ycov, dec_gb,
                                           nullptr, nullptr, nullptr);
        k_cell<<<gs_cell, 512, SM_BYTES>>>(1, 1, t, x, ycov, dec_ub,
                                           proj_W, proj_b, out);
    }
}

// round 12
// speedup vs baseline: 1.0295x; 1.0295x over previous
#include <cuda_runtime.h>
#include <cuda_fp16.h>
#include <math.h>

// ---------------- problem constants ----------------
#define BB   32
#define TT   12
#define NN   512
#define HID  64
#define EMB  10
#define BN   (BB*NN)     // 16384

// Feature K layout for the weight GEMM (208 rows):
//  0..63   X (h or z*h) | 64..127 S@X | 128..191 2S^2X-X
//  192..197 [x0,x1,Sx0,Sx1,S2x0,S2x1] | 198..207 zero pad

// ---------------- dynamic smem layout (bytes) ----------------
#define TILEH   3072        // halves per 128x24 tile
#define TILEB   6144
#define OFF_PAN 0           // 13 tiles            -> 79872
#define OFF_SS  79872       // 3 stages x 2 tiles  -> 36864
#define OFF_S2  116736      // 3 stages x 2 tiles  -> 36864
#define OFF_XB  153600      // 3 stages x 2x(64x24)-> 18432
#define OFF_GO  172032      // 512 floats          -> 2048
#define SM_BYTES 174080

// ---------------- device scratch ----------------
__device__ float  g_h[BN*HID];
__device__ float  g_r[BN*HID];
__device__ __half g_x0 [BN*64];          // h, row-major
__device__ __half g_x0T[BB*64*NN];       // h, [b][c][n]
__device__ __half g_x1 [BN*64];          // z*h, row-major
__device__ __half g_x1T[BB*64*NN];
__device__ float  g_sup_en_f[NN*NN];
__device__ __half g_sup_en_h[NN*NN];
__device__ float  g_sup_de_f[(size_t)BB*NN*NN];
__device__ __half g_sup_de_h[(size_t)BB*NN*NN];
__device__ float  g_s2_en_f[NN*NN];
__device__ __half g_s2_en_h[NN*NN];
__device__ float  g_s2_de_f[(size_t)BB*NN*NN];
__device__ __half g_s2_de_h[(size_t)BB*NN*NN];
__device__ float  g_ne[BN*EMB];
__device__ float  g_go[BN];
__device__ float  g_xf1[BN*24];
__device__ float  g_xf2[BN*24];
__device__ float  g_yf1[BN*TT];
__device__ float  g_yf2[BN*TT];
// transposed fp16 weights: [n][208]
__device__ __half g_WgeT[128*208];
__device__ __half g_WgdT[128*208];
__device__ __half g_WueT[64*208];
__device__ __half g_WudT[64*208];

__device__ __forceinline__ int wmap(int c) {
    if (c < 64)  return c + 2;
    if (c < 128) return c + 4;
    if (c < 192) return c + 6;
    return ((c - 192) >> 1) * 66 + (c & 1);
}

// ---------------- mma helpers ----------------
__device__ __forceinline__ unsigned f2tf(float f) {
    unsigned u;
    asm("cvt.rna.tf32.f32 %0, %1;" : "=r"(u) : "f"(f));
    return u;
}
__device__ __forceinline__ void mma_tf32(float* d,
    unsigned a0, unsigned a1, unsigned a2, unsigned a3,
    unsigned b0, unsigned b1) {
    asm volatile(
        "mma.sync.aligned.m16n8k8.row.col.f32.tf32.tf32.f32 "
        "{%0,%1,%2,%3}, {%4,%5,%6,%7}, {%8,%9}, {%0,%1,%2,%3};\n"
        : "+f"(d[0]), "+f"(d[1]), "+f"(d[2]), "+f"(d[3])
        : "r"(a0), "r"(a1), "r"(a2), "r"(a3), "r"(b0), "r"(b1));
}
__device__ __forceinline__ void mma_f16(float* d,
    unsigned a0, unsigned a1, unsigned a2, unsigned a3,
    unsigned b0, unsigned b1) {
    asm volatile(
        "mma.sync.aligned.m16n8k16.row.col.f32.f16.f16.f32 "
        "{%0,%1,%2,%3}, {%4,%5,%6,%7}, {%8,%9}, {%0,%1,%2,%3};\n"
        : "+f"(d[0]), "+f"(d[1]), "+f"(d[2]), "+f"(d[3])
        : "r"(a0), "r"(a1), "r"(a2), "r"(a3), "r"(b0), "r"(b1));
}
__device__ __forceinline__ void ldsm_x4(unsigned& r0, unsigned& r1,
                                        unsigned& r2, unsigned& r3, unsigned addr) {
    asm volatile("ldmatrix.sync.aligned.m8n8.x4.shared.b16 {%0,%1,%2,%3}, [%4];"
        : "=r"(r0), "=r"(r1), "=r"(r2), "=r"(r3) : "r"(addr));
}

__device__ __forceinline__ void cpa16(void* smem, const void* g) {
    unsigned s = (unsigned)__cvta_generic_to_shared(smem);
    asm volatile("cp.async.cg.shared.global [%0], [%1], 16;\n" :: "r"(s), "l"(g));
}
#define CP_COMMIT() asm volatile("cp.async.commit_group;\n" ::: "memory")
#define CP_WAIT1()  asm volatile("cp.async.wait_group 1;\n" ::: "memory")
#define CP_WAIT0()  asm volatile("cp.async.wait_group 0;\n" ::: "memory")

// ---------------- init ----------------
__global__ void k_zero() {
    size_t i = (size_t)blockIdx.x*blockDim.x + threadIdx.x;
    size_t st = (size_t)gridDim.x*blockDim.x;
    const __half hz = __float2half(0.f);
    for (size_t j=i; j<(size_t)BN*64; j+=st) { g_x0[j] = hz; g_x0T[j] = hz; }
    for (size_t j=i; j<BN*HID; j+=st) g_h[j]  = 0.f;
    for (size_t j=i; j<BN;     j+=st) g_go[j] = 0.f;
}

// ---------------- weight reorder (transposed fp16) --------------------------
__global__ void k_prep(const float* __restrict__ W, int which) {
    int nc = (which < 2) ? 128 : 64;
    __half* dst = (which == 0) ? g_WgeT : (which == 1) ? g_WgdT
               : (which == 2) ? g_WueT : g_WudT;
    int idx = blockIdx.x*blockDim.x + threadIdx.x;
    if (idx >= 208*nc) return;
    int c = idx / nc, o = idx - c*nc;
    float v = 0.f;
    if (c < 198) v = W[wmap(c)*nc + o];
    dst[(size_t)o*208 + c] = __float2half(v);
}

// ---------------- supports (fp32 + fp16 copies) ----------------
__global__ void k_support_en(const float* __restrict__ emb) {
    int n = blockIdx.x, tid = threadIdx.x;
    __shared__ float embn[EMB];
    __shared__ float row[NN];
    __shared__ float red[256];
    if (tid < EMB) embn[tid] = emb[n*EMB + tid];
    __syncthreads();
    for (int m=tid; m<NN; m+=256) {
        float s = 0.f;
        #pragma unroll
        for (int e=0; e<EMB; e++) s += embn[e]*emb[m*EMB+e];
        row[m] = fmaxf(s, 0.f);
    }
    __syncthreads();
    float lm = -1e30f;
    for (int m=tid; m<NN; m+=256) lm = fmaxf(lm, row[m]);
    red[tid]=lm; __syncthreads();
    for (int s=128;s>0;s>>=1){ if(tid<s) red[tid]=fmaxf(red[tid],red[tid+s]); __syncthreads(); }
    float mx = red[0]; __syncthreads();
    float ls = 0.f;
    for (int m=tid; m<NN; m+=256){ float e=expf(row[m]-mx); row[m]=e; ls+=e; }
    red[tid]=ls; __syncthreads();
    for (int s=128;s>0;s>>=1){ if(tid<s) red[tid]+=red[tid+s]; __syncthreads(); }
    float inv = 1.f/red[0];
    for (int m=tid; m<NN; m+=256) {
        float v = row[m]*inv;
        g_sup_en_f[n*NN+m] = v;
        g_sup_en_h[n*NN+m] = __float2half(v);
    }
}

__global__ void k_support_de() {
    int bn = blockIdx.x;
    int b = bn >> 9, n = bn & 511;
    int tid = threadIdx.x;
    const float* neb = g_ne + (size_t)b*NN*EMB;
    __shared__ float embn[EMB];
    __shared__ float row[NN];
    __shared__ float red[256];
    if (tid < EMB) embn[tid] = neb[n*EMB + tid];
    __syncthreads();
    for (int m=tid; m<NN; m+=256) {
        float s = 0.f;
        #pragma unroll
        for (int e=0; e<EMB; e++) s += embn[e]*neb[m*EMB+e];
        row[m] = fmaxf(s, 0.f);
    }
    __syncthreads();
    float lm = -1e30f;
    for (int m=tid; m<NN; m+=256) lm = fmaxf(lm, row[m]);
    red[tid]=lm; __syncthreads();
    for (int s=128;s>0;s>>=1){ if(tid<s) red[tid]=fmaxf(red[tid],red[tid+s]); __syncthreads(); }
    float mx = red[0]; __syncthreads();
    float ls = 0.f;
    for (int m=tid; m<NN; m+=256){ float e=expf(row[m]-mx); row[m]=e; ls+=e; }
    red[tid]=ls; __syncthreads();
    for (int s=128;s>0;s>>=1){ if(tid<s) red[tid]+=red[tid+s]; __syncthreads(); }
    float inv = 1.f/red[0];
    size_t base = (size_t)b*NN*NN + (size_t)n*NN;
    for (int m=tid; m<NN; m+=256) {
        float v = row[m]*inv;
        g_sup_de_f[base+m] = v;
        g_sup_de_h[base+m] = __float2half(v);
    }
}

// ---------------- S2 = S @ S  (tf32 MMA on fp32 S; dual-format output) ------
__global__ void __launch_bounds__(256) k_sq(int deFlag) {
    __shared__ float As[3][128*20];
    __shared__ float Bs[3][16*72];
    const int b  = blockIdx.z;
    const int m0 = blockIdx.x*128;
    const int n0 = blockIdx.y*64;
    const int tid = threadIdx.x;
    const int warp = tid >> 5, lane = tid & 31;
    const int mw = warp & 3, nw = warp >> 2;
    const int tq = lane >> 2, tr = lane & 3;
    const float* S = deFlag ? g_sup_de_f + (size_t)b*NN*NN : g_sup_en_f;
    float*  Df = deFlag ? g_s2_de_f + (size_t)b*NN*NN : g_s2_en_f;
    __half* Dh = deFlag ? g_s2_de_h + (size_t)b*NN*NN : g_s2_en_h;
    const int lr = tid >> 1, lc = (tid & 1)*8;
    const int bk = tid >> 4, bn = (tid & 15)*4;

    float acc[2][4][4] = {};

#define SQ_LOAD(st, k0) do { \
    cpa16(&As[st][lr*20+lc],   &S[(size_t)(m0+lr)*NN + (k0)+lc]); \
    cpa16(&As[st][lr*20+lc+4], &S[(size_t)(m0+lr)*NN + (k0)+lc+4]); \
    cpa16(&Bs[st][bk*72+bn],   &S[(size_t)((k0)+bk)*NN + n0 + bn]); \
} while(0)

    SQ_LOAD(0, 0);  CP_COMMIT();
    SQ_LOAD(1, 16); CP_COMMIT();
    for (int kt = 0; kt < 32; kt++) {
        CP_WAIT1();
        __syncthreads();
        if (kt < 30) SQ_LOAD((kt+2)%3, (kt+2)*16);
        CP_COMMIT();
        const float* Ab = As[kt%3];
        const float* Bb = Bs[kt%3];
        #pragma unroll
        for (int ks = 0; ks < 16; ks += 8) {
            unsigned a[2][4], bb[4][2];
            #pragma unroll
            for (int mi = 0; mi < 2; mi++) {
                int r = mw*32 + mi*16 + tq;
                a[mi][0] = f2tf(Ab[r*20 + ks + tr]);
                a[mi][1] = f2tf(Ab[(r+8)*20 + ks + tr]);
                a[mi][2] = f2tf(Ab[r*20 + ks + tr + 4]);
                a[mi][3] = f2tf(Ab[(r+8)*20 + ks + tr + 4]);
            }
            #pragma unroll
            for (int nj = 0; nj < 4; nj++) {
                int c = nw*32 + nj*8 + tq;
                bb[nj][0] = f2tf(Bb[(ks+tr)*72 + c]);
                bb[nj][1] = f2tf(Bb[(ks+tr+4)*72 + c]);
            }
            #pragma unroll
            for (int mi = 0; mi < 2; mi++)
                #pragma unroll
                for (int nj = 0; nj < 4; nj++)
                    mma_tf32(acc[mi][nj], a[mi][0], a[mi][1], a[mi][2], a[mi][3],
                             bb[nj][0], bb[nj][1]);
        }
    }
    __syncthreads();
    #pragma unroll
    for (int mi = 0; mi < 2; mi++) {
        int r0 = m0 + mw*32 + mi*16 + tq;
        #pragma unroll
        for (int nj = 0; nj < 4; nj++) {
            int c = n0 + nw*32 + nj*8 + tr*2;
            #pragma unroll
            for (int hh = 0; hh < 2; hh++) {
                int rr = r0 + hh*8;
                float va = acc[mi][nj][hh*2], vb = acc[mi][nj][hh*2+1];
                *(float2*)&Df[(size_t)rr*NN + c] = make_float2(va, vb);
                *(__half2*)&Dh[(size_t)rr*NN + c] = __floats2half2_rn(va, vb);
            }
        }
    }
#undef SQ_LOAD
}

// ---------------- x/ycov feature precompute ---------------------------------
__global__ void __launch_bounds__(256) k_pre_enc(const float* __restrict__ x) {
    __shared__ float xsh[512*24];
    int b = blockIdx.y, m0 = blockIdx.x*32, z = blockIdx.z;
    int tid = threadIdx.x;
    for (int idx = tid; idx < 512*24; idx += 256) {
        int k = idx/24, tc = idx%24;
        int t = tc>>1, c = tc&1;
        xsh[idx] = x[(((size_t)b*TT+t)*NN + k)*2 + c];
    }
    __syncthreads();
    int rl = tid>>3, kh = (tid>>2)&1, cg = tid&3;
    int row = m0 + rl, g = cg*6;
    float acc[6] = {};
    const float* Srow = (z ? g_s2_en_f : g_sup_en_f) + (size_t)row*NN + kh*256;
    const float* xp = &xsh[kh*256*24];
    for (int k=0;k<256;k+=4){
        float4 s = *(const float4*)&Srow[k];
        #pragma unroll
        for (int j=0;j<6;j++)
            acc[j] += s.x*xp[(k+0)*24+g+j] + s.y*xp[(k+1)*24+g+j]
                    + s.z*xp[(k+2)*24+g+j] + s.w*xp[(k+3)*24+g+j];
    }
    #pragma unroll
    for (int j=0;j<6;j++) acc[j] += __shfl_xor_sync(0xffffffffu, acc[j], 4);
    if (kh == 0) {
        #pragma unroll
        for (int j=0;j<6;j++) {
            int col = g + j;
            if (z == 0) g_xf1[((size_t)b*NN + row)*24 + col] = acc[j];
            else {
                int t = col>>1, c = col&1;
                g_xf2[((size_t)b*NN + row)*24 + col] =
                    2.f*acc[j] - x[(((size_t)b*TT+t)*NN + row)*2 + c];
            }
        }
    }
}

__global__ void __launch_bounds__(256) k_pre_dec(const float* __restrict__ ycov) {
    __shared__ float ysh[512*12];
    int b = blockIdx.y, m0 = blockIdx.x*32, z = blockIdx.z;
    int tid = threadIdx.x;
    for (int idx = tid; idx < 512*12; idx += 256) {
        int k = idx/12, t = idx%12;
        ysh[idx] = ycov[((size_t)b*TT+t)*NN + k];
    }
    __syncthreads();
    int rl = tid>>3, kh = (tid>>2)&1, cg = tid&3;
    int row = m0 + rl, g = cg*3;
    float acc[3] = {};
    const float* Srow = (z ? g_s2_de_f : g_sup_de_f)
                        + (size_t)b*NN*NN + (size_t)row*NN + kh*256;
    const float* yp = &ysh[kh*256*12];
    for (int k=0;k<256;k+=4){
        float4 s = *(const float4*)&Srow[k];
        #pragma unroll
        for (int j=0;j<3;j++)
            acc[j] += s.x*yp[(k+0)*12+g+j] + s.y*yp[(k+1)*12+g+j]
                    + s.z*yp[(k+2)*12+g+j] + s.w*yp[(k+3)*12+g+j];
    }
    #pragma unroll
    for (int j=0;j<3;j++) acc[j] += __shfl_xor_sync(0xffffffffu, acc[j], 4);
    if (kh == 0) {
        #pragma unroll
        for (int j=0;j<3;j++) {
            int t = g + j;
            if (z == 0) g_yf1[((size_t)b*NN + row)*12 + t] = acc[j];
            else        g_yf2[((size_t)b*NN + row)*12 + t] =
                            2.f*acc[j] - ycov[((size_t)b*TT+t)*NN + row];
        }
    }
}

// ---------------- fused cell-phase kernel (256 thr, k32 phase A) -------------
__global__ void __launch_bounds__(256) k_cell(
    int phase, int deFlag, int t,
    const float* __restrict__ x, const float* __restrict__ ycov,
    const float* __restrict__ bias,
    const float* __restrict__ pW, const float* __restrict__ pb,
    float* __restrict__ out)
{
    extern __shared__ char smx[];
    __half* PAN = (__half*)(smx + OFF_PAN);
    __half* SS  = (__half*)(smx + OFF_SS);
    __half* S2S = (__half*)(smx + OFF_S2);
    __half* XB  = (__half*)(smx + OFF_XB);
    float*  GOs = (float*)(smx + OFF_GO);
    __shared__ float pr[2][128];

    const int b  = blockIdx.y;
    const int m0 = blockIdx.x*128;
    const int tid = threadIdx.x;
    const int warp = tid >> 5, lane = tid & 31;
    const int mw = warp & 3, nw = warp >> 2;
    const int tq = lane >> 2, tr = lane & 3;

    // ldmatrix lane geometry
    const int l8 = lane & 7, mt = lane >> 3;
    const int arow = l8 + (mt & 1)*8;
    const int acol = (mt >> 1)*8;
    const int brow = l8 + (mt >> 1)*8;
    const int bcol = (mt & 1)*8;
    const unsigned aOff0 = ((mw*32 + arow)*24 + acol)*2;
    const unsigned aOff1 = aOff0 + 16*48;
    const unsigned bOff0 = ((nw*32 + brow)*24 + bcol)*2;
    const unsigned bOff1 = bOff0 + 16*48;
    const unsigned uPAN = (unsigned)__cvta_generic_to_shared(PAN);
    const unsigned uSS  = (unsigned)__cvta_generic_to_shared(SS);
    const unsigned uS2  = (unsigned)__cvta_generic_to_shared(S2S);
    const unsigned uXB  = (unsigned)__cvta_generic_to_shared(XB);

    const __half* Sh  = deFlag ? g_sup_de_h + (size_t)b*NN*NN : g_sup_en_h;
    const __half* S2h = deFlag ? g_s2_de_h  + (size_t)b*NN*NN : g_s2_en_h;
    const __half* Xrow = (phase == 0) ? g_x0 : g_x1;
    const __half* XT   = (phase == 0) ? g_x0T : g_x1T;

    // ---- preload panel tiles 0..3 (X own rows) ----
    #pragma unroll
    for (int i = 0; i < 4; i++) {
        int ch = tid + i*256;
        int tI = ch >> 8, rw = (ch >> 1) & 127, off = (ch & 1)*8;
        cpa16(&PAN[tI*TILEH + rw*24 + off],
              &Xrow[((size_t)b*NN + m0 + rw)*64 + tI*16 + off]);
    }
    if (deFlag) {
        GOs[tid]       = g_go[(size_t)b*NN + tid];
        GOs[tid + 256] = g_go[(size_t)b*NN + tid + 256];
    }
    CP_COMMIT();

    // ---- phase A: Y1 = S@X, Y2raw = S2@X (K=512, 16 k32-stages) ----
    const int lrA = tid >> 1, loA = (tid & 1)*8;

    float acc1[2][4][4] = {};
    float acc2[2][4][4] = {};
    float d1 = 0.f, d2 = 0.f;
    const int mvrow = tid >> 1, mvh = (tid & 1)*8;

#define PA_LOAD(st, k0) do { \
    cpa16(&SS [(st)*2*TILEH + lrA*24 + loA],         &Sh [(size_t)(m0+lrA)*NN + (k0)+loA]); \
    cpa16(&SS [(st)*2*TILEH + TILEH + lrA*24 + loA], &Sh [(size_t)(m0+lrA)*NN + (k0)+16+loA]); \
    cpa16(&S2S[(st)*2*TILEH + lrA*24 + loA],         &S2h[(size_t)(m0+lrA)*NN + (k0)+loA]); \
    cpa16(&S2S[(st)*2*TILEH + TILEH + lrA*24 + loA], &S2h[(size_t)(m0+lrA)*NN + (k0)+16+loA]); \
    if (tid < 128) { \
        cpa16(&XB[(st)*3072 + lrA*24 + loA],        &XT[((size_t)b*64 + lrA)*NN + (k0)+loA]); \
        cpa16(&XB[(st)*3072 + 1536 + lrA*24 + loA], &XT[((size_t)b*64 + lrA)*NN + (k0)+16+loA]); \
    } \
} while(0)

    PA_LOAD(0, 0);  CP_COMMIT();
    PA_LOAD(1, 32); CP_COMMIT();
    for (int kt = 0; kt < 16; kt++) {
        CP_WAIT1();
        __syncthreads();
        if (kt < 14) PA_LOAD((kt+2)%3, (kt+2)*32);
        CP_COMMIT();
        #pragma unroll
        for (int sub = 0; sub < 2; sub++) {
            const unsigned sb  = uSS + ((kt%3)*2 + sub)*TILEB;
            const unsigned s2b = uS2 + ((kt%3)*2 + sub)*TILEB;
            const unsigned xb  = uXB + (kt%3)*6144 + sub*3072;
            unsigned a[2][4], a2[2][4], bb[4][2];
            ldsm_x4(a [0][0], a [0][1], a [0][2], a [0][3], sb  + aOff0);
            ldsm_x4(a [1][0], a [1][1], a [1][2], a [1][3], sb  + aOff1);
            ldsm_x4(a2[0][0], a2[0][1], a2[0][2], a2[0][3], s2b + aOff0);
            ldsm_x4(a2[1][0], a2[1][1], a2[1][2], a2[1][3], s2b + aOff1);
            ldsm_x4(bb[0][0], bb[0][1], bb[1][0], bb[1][1], xb + bOff0);
            ldsm_x4(bb[2][0], bb[2][1], bb[3][0], bb[3][1], xb + bOff1);
            #pragma unroll
            for (int mi = 0; mi < 2; mi++)
                #pragma unroll
                for (int nj = 0; nj < 4; nj++) {
                    mma_f16(acc1[mi][nj], a [mi][0], a [mi][1], a [mi][2], a [mi][3],
                            bb[nj][0], bb[nj][1]);
                    mma_f16(acc2[mi][nj], a2[mi][0], a2[mi][1], a2[mi][2], a2[mi][3],
                            bb[nj][0], bb[nj][1]);
                }
            if (deFlag) {
                const __half* Ab  = SS  + ((kt%3)*2 + sub)*TILEH;
                const __half* A2b = S2S + ((kt%3)*2 + sub)*TILEH;
                const __half2* ap  = (const __half2*)&Ab [mvrow*24 + mvh];
                const __half2* a2p = (const __half2*)&A2b[mvrow*24 + mvh];
                const float* gop = &GOs[kt*32 + sub*16 + mvh];
                #pragma unroll
                for (int j = 0; j < 4; j++) {
                    float2 v  = __half22float2(ap[j]);
                    float2 v2 = __half22float2(a2p[j]);
                    d1 += v.x*gop[2*j] + v.y*gop[2*j+1];
                    d2 += v2.x*gop[2*j] + v2.y*gop[2*j+1];
                }
            }
        }
    }
    CP_WAIT0();
    __syncthreads();

    // ---- write Y1 (tiles 4..7), Y2 = 2*acc2 - X (tiles 8..11) ----
    #pragma unroll
    for (int mi = 0; mi < 2; mi++) {
        int r = mw*32 + mi*16 + tq;
        #pragma unroll
        for (int nj = 0; nj < 4; nj++) {
            int c = nw*32 + nj*8 + tr*2;
            int tI = c >> 4, kk = c & 15;
            #pragma unroll
            for (int hh = 0; hh < 2; hh++) {
                int rr = r + hh*8;
                float v1a = acc1[mi][nj][hh*2], v1b = acc1[mi][nj][hh*2+1];
                float v2a = acc2[mi][nj][hh*2], v2b = acc2[mi][nj][hh*2+1];
                float xa  = __half2float(PAN[tI*TILEH + rr*24 + kk]);
                float xb2 = __half2float(PAN[tI*TILEH + rr*24 + kk + 1]);
                *(__half2*)&PAN[(4+tI)*TILEH + rr*24 + kk] =
                    __floats2half2_rn(v1a, v1b);
                *(__half2*)&PAN[(8+tI)*TILEH + rr*24 + kk] =
                    __floats2half2_rn(2.f*v2a - xa, 2.f*v2b - xb2);
            }
        }
    }

    // ---- tile 12: extra features ----
    if (deFlag) {
        d1 += __shfl_xor_sync(0xffffffffu, d1, 1);
        d2 += __shfl_xor_sync(0xffffffffu, d2, 1);
        if ((tid & 1) == 0) {
            int rw = tid >> 1;
            size_t gr = (size_t)b*NN + m0 + rw;
            float go = GOs[m0 + rw];
            __half* T = &PAN[12*TILEH + rw*24];
            T[0] = __float2half(go);
            T[1] = __float2half(ycov[((size_t)b*TT + t)*NN + m0 + rw]);
            T[2] = __float2half(d1);
            T[3] = __float2half(g_yf1[gr*12 + t]);
            T[4] = __float2half(2.f*d2 - go);
            T[5] = __float2half(g_yf2[gr*12 + t]);
            #pragma unroll
            for (int j = 6; j < 16; j++) T[j] = __float2half(0.f);
        }
    } else {
        if (tid < 128) {
            int rw = tid;
            size_t gr = (size_t)b*NN + m0 + rw;
            const float* xp = &x[(((size_t)b*TT + t)*NN + m0 + rw)*2];
            __half* T = &PAN[12*TILEH + rw*24];
            T[0] = __float2half(xp[0]);
            T[1] = __float2half(xp[1]);
            T[2] = __float2half(g_xf1[gr*24 + t*2 + 0]);
            T[3] = __float2half(g_xf1[gr*24 + t*2 + 1]);
            T[4] = __float2half(g_xf2[gr*24 + t*2 + 0]);
            T[5] = __float2half(g_xf2[gr*24 + t*2 + 1]);
            #pragma unroll
            for (int j = 6; j < 16; j++) T[j] = __float2half(0.f);
        }
    }
    __syncthreads();

    // ---- phase B: weight GEMM over K=208 from the panel (k16 pipeline) -----
    if (phase == 0) {
        const __half* WT = deFlag ? g_WgdT : g_WgeT;
        float acc[2][8][4] = {};
        const unsigned bG0 = ((nw*64 + brow)*24 + bcol)*2;
#define WB_LOAD128(st, k0) do { \
    int n_ = tid >> 1, of_ = (tid & 1)*8; \
    cpa16(&SS[(st)*TILEH + n_*24 + of_], &WT[(size_t)n_*208 + (k0)+of_]); \
} while(0)
        WB_LOAD128(0, 0);  CP_COMMIT();
        WB_LOAD128(1, 16); CP_COMMIT();
        for (int kt = 0; kt < 13; kt++) {
            CP_WAIT1();
            __syncthreads();
            if (kt < 11) WB_LOAD128((kt+2)%3, (kt+2)*16);
            CP_COMMIT();
            const unsigned pb_ = uPAN + kt*TILEB;
            const unsigned wb  = uSS + (kt%3)*TILEB;
            unsigned a[2][4], bb[8][2];
            ldsm_x4(a[0][0], a[0][1], a[0][2], a[0][3], pb_ + aOff0);
            ldsm_x4(a[1][0], a[1][1], a[1][2], a[1][3], pb_ + aOff1);
            #pragma unroll
            for (int j = 0; j < 4; j++)
                ldsm_x4(bb[2*j][0], bb[2*j][1], bb[2*j+1][0], bb[2*j+1][1],
                        wb + bG0 + j*16*48);
            #pragma unroll
            for (int mi = 0; mi < 2; mi++)
                #pragma unroll
                for (int nj = 0; nj < 8; nj++)
                    mma_f16(acc[mi][nj], a[mi][0], a[mi][1], a[mi][2], a[mi][3],
                            bb[nj][0], bb[nj][1]);
        }
        // epilogue: z = sigmoid -> z*h into g_x1/g_x1T ; r into g_r
        #pragma unroll
        for (int mi = 0; mi < 2; mi++) {
            int r0 = mw*32 + mi*16 + tq;
            #pragma unroll
            for (int nj = 0; nj < 8; nj++) {
                int c = nw*64 + nj*8 + tr*2;
                #pragma unroll
                for (int hh = 0; hh < 2; hh++) {
                    int ln = m0 + r0 + hh*8;
                    size_t row = (size_t)b*NN + ln;
                    float va = acc[mi][nj][hh*2], vb = acc[mi][nj][hh*2+1];
                    float za = 1.f/(1.f + expf(-(va + bias[c])));
                    float zb = 1.f/(1.f + expf(-(vb + bias[c+1])));
                    if (c < 64) {
                        float ha = za * g_h[row*HID + c];
                        float hb = zb * g_h[row*HID + c+1];
                        *(__half2*)&g_x1[row*64 + c] = __floats2half2_rn(ha, hb);
                        g_x1T[((size_t)b*64 + c  )*NN + ln] = __float2half(ha);
                        g_x1T[((size_t)b*64 + c+1)*NN + ln] = __float2half(hb);
                    } else {
                        g_r[row*HID + (c-64)]   = za;
                        g_r[row*HID + (c-64)+1] = zb;
                    }
                }
            }
        }
#undef WB_LOAD128
    } else {
        const __half* WT = deFlag ? g_WudT : g_WueT;
        float acc[2][4][4] = {};
#define WB_LOAD64(st, k0) do { \
    if (tid < 128) { int n_ = tid >> 1, of_ = (tid & 1)*8; \
        cpa16(&SS[(st)*1536 + n_*24 + of_], &WT[(size_t)n_*208 + (k0)+of_]); } \
} while(0)
        WB_LOAD64(0, 0);  CP_COMMIT();
        WB_LOAD64(1, 16); CP_COMMIT();
        for (int kt = 0; kt < 13; kt++) {
            CP_WAIT1();
            __syncthreads();
            if (kt < 11) WB_LOAD64((kt+2)%3, (kt+2)*16);
            CP_COMMIT();
            const unsigned pb_ = uPAN + kt*TILEB;
            const unsigned wb  = uSS + (kt%3)*3072;
            unsigned a[2][4], bb[4][2];
            ldsm_x4(a[0][0], a[0][1], a[0][2], a[0][3], pb_ + aOff0);
            ldsm_x4(a[1][0], a[1][1], a[1][2], a[1][3], pb_ + aOff1);
            ldsm_x4(bb[0][0], bb[0][1], bb[1][0], bb[1][1], wb + bOff0);
            ldsm_x4(bb[2][0], bb[2][1], bb[3][0], bb[3][1], wb + bOff1);
            #pragma unroll
            for (int mi = 0; mi < 2; mi++)
                #pragma unroll
                for (int nj = 0; nj < 4; nj++)
                    mma_f16(acc[mi][nj], a[mi][0], a[mi][1], a[mi][2], a[mi][3],
                            bb[nj][0], bb[nj][1]);
        }
        // epilogue: h update (+ projection for decoder)
        const bool doProj = (deFlag != 0);
        float rowsum[2][2] = {};
        #pragma unroll
        for (int mi = 0; mi < 2; mi++) {
            int r0 = mw*32 + mi*16 + tq;
            #pragma unroll
            for (int nj = 0; nj < 4; nj++) {
                int c = nw*32 + nj*8 + tr*2;
                #pragma unroll
                for (int hh = 0; hh < 2; hh++) {
                    int ln = m0 + r0 + hh*8;
                    size_t row = (size_t)b*NN + ln;
                    float hn2[2];
                    #pragma unroll
                    for (int jj = 0; jj < 2; jj++) {
                        int o = c + jj;
                        float hc = tanhf(acc[mi][nj][hh*2+jj] + bias[o]);
                        float r  = g_r[row*HID + o];
                        float h  = g_h[row*HID + o];
                        float hn = r*h + (1.f - r)*hc;
                        g_h[row*HID + o] = hn;
                        g_x0T[((size_t)b*64 + o)*NN + ln] = __float2half(hn);
                        hn2[jj] = hn;
                        if (doProj) rowsum[mi][hh] += hn * pW[o];
                    }
                    *(__half2*)&g_x0[row*64 + c] = __floats2half2_rn(hn2[0], hn2[1]);
                }
            }
        }
        if (doProj) {
            #pragma unroll
            for (int mi = 0; mi < 2; mi++)
                #pragma unroll
                for (int hh = 0; hh < 2; hh++) {
                    float v = rowsum[mi][hh];
                    v += __shfl_xor_sync(0xffffffffu, v, 1);
                    v += __shfl_xor_sync(0xffffffffu, v, 2);
                    if (tr == 0) pr[nw][mw*32 + mi*16 + tq + hh*8] = v;
                }
            __syncthreads();
            if (tid < 128) {
                int n = m0 + tid;
                float go = pr[0][tid] + pr[1][tid] + pb[0];
                g_go[(size_t)b*NN + n] = go;
                out[((size_t)b*TT + t)*NN + n] = go;
            }
        }
#undef WB_LOAD64
    }
#undef PA_LOAD
}

// ---------------- hyper projection ------------------------------------------
__global__ void k_hyper(const float* __restrict__ hW, const float* __restrict__ hb) {
    int idx = blockIdx.x*blockDim.x + threadIdx.x;
    if (idx >= BN*EMB) return;
    int bn = idx / EMB, e = idx % EMB;
    float s = hb[e];
    #pragma unroll
    for (int k = 0; k < HID; k++) s += g_h[(size_t)bn*HID + k] * hW[k*EMB + e];
    g_ne[idx] = s;
}

// ---------------- orchestration ---------------------------------------------
extern "C" void kernel_launch(void* const* d_in, const int* in_sizes, int n_in,
                              void* d_out, int out_size) {
    const float* x       = (const float*)d_in[0];
    const float* ycov    = (const float*)d_in[1];
    const float* emb     = (const float*)d_in[2];
    const float* enc_gW  = (const float*)d_in[3];
    const float* enc_gb  = (const float*)d_in[4];
    const float* enc_uW  = (const float*)d_in[5];
    const float* enc_ub  = (const float*)d_in[6];
    const float* dec_gW  = (const float*)d_in[7];
    const float* dec_gb  = (const float*)d_in[8];
    const float* dec_uW  = (const float*)d_in[9];
    const float* dec_ub  = (const float*)d_in[10];
    const float* proj_W  = (const float*)d_in[11];
    const float* proj_b  = (const float*)d_in[12];
    const float* hyper_W = (const float*)d_in[13];
    const float* hyper_b = (const float*)d_in[14];
    float* out = (float*)d_out;

    static int smem_set = 0;
    if (!smem_set) {
        cudaFuncSetAttribute(k_cell, cudaFuncAttributeMaxDynamicSharedMemorySize,
                             SM_BYTES);
        smem_set = 1;
    }

    dim3 gs_cell(4, BB);
    dim3 gs_sq_en(4, 8, 1);
    dim3 gs_sq_de(4, 8, BB);
    dim3 gs_pre(16, BB, 2);

    k_zero<<<1024, 256>>>();
    k_prep<<<(208*128+255)/256, 256>>>(enc_gW, 0);
    k_prep<<<(208*128+255)/256, 256>>>(dec_gW, 1);
    k_prep<<<(208*64+255)/256, 256>>>(enc_uW, 2);
    k_prep<<<(208*64+255)/256, 256>>>(dec_uW, 3);
    k_support_en<<<NN, 256>>>(emb);
    k_sq<<<gs_sq_en, 256>>>(0);
    k_pre_enc<<<gs_pre, 256>>>(x);

    for (int t = 0; t < TT; t++) {
        k_cell<<<gs_cell, 256, SM_BYTES>>>(0, 0, t, x, ycov, enc_gb,
                                           nullptr, nullptr, nullptr);
        k_cell<<<gs_cell, 256, SM_BYTES>>>(1, 0, t, x, ycov, enc_ub,
                                           nullptr, nullptr, nullptr);
    }

    k_hyper<<<(BN*EMB + 255)/256, 256>>>(hyper_W, hyper_b);
    k_support_de<<<BN, 256>>>();
    k_sq<<<gs_sq_de, 256>>>(1);
    k_pre_dec<<<gs_pre, 256>>>(ycov);

    for (int t = 0; t < TT; t++) {
        k_cell<<<gs_cell, 256, SM_BYTES>>>(0, 1, t, x, ycov, dec_gb,
                                           nullptr, nullptr, nullptr);
        k_cell<<<gs_cell, 256, SM_BYTES>>>(1, 1, t, x, ycov, dec_ub,
                                           proj_W, proj_b, out);
    }
}

// round 14
// speedup vs baseline: 1.0318x; 1.0023x over previous
#include <cuda_runtime.h>
#include <cuda_fp16.h>
#include <math.h>

// ---------------- problem constants ----------------
#define BB   32
#define TT   12
#define NN   512
#define HID  64
#define EMB  10
#define BN   (BB*NN)     // 16384

// Feature K layout for the weight GEMM (208 rows):
//  0..63   X (h or z*h) | 64..127 S@X | 128..191 2S^2X-X
//  192..197 [x0,x1,Sx0,Sx1,S2x0,S2x1] | 198..207 zero pad

// ---------------- dynamic smem layout (halves / bytes), M-tile = 64 ---------
#define TILEH   1536        // halves per 64x24 tile
#define TILEB   3072        // bytes per 64x24 tile
#define OFF_PAN 0           // 13 tiles -> 39936 B
#define OFF_SS  39936       // 3 stages S (64x24)   -> 9216 B   (also W staging)
#define OFF_S2  49152       // 3 stages S2          -> 9216 B
#define OFF_XB  58368       // 3 stages X B-tile    -> 9216 B
#define OFF_GO  67584       // 512 floats           -> 2048 B
#define SM_BYTES 69632

// ---------------- device scratch ----------------
__device__ float  g_h[BN*HID];
__device__ float  g_r[BN*HID];
__device__ __half g_x0 [BN*64];          // h, row-major
__device__ __half g_x0T[BB*64*NN];       // h, [b][c][n]
__device__ __half g_x1 [BN*64];          // z*h, row-major
__device__ __half g_x1T[BB*64*NN];
__device__ float  g_sup_en_f[NN*NN];
__device__ __half g_sup_en_h[NN*NN];
__device__ float  g_sup_de_f[(size_t)BB*NN*NN];
__device__ __half g_sup_de_h[(size_t)BB*NN*NN];
__device__ float  g_s2_en_f[NN*NN];
__device__ __half g_s2_en_h[NN*NN];
__device__ float  g_s2_de_f[(size_t)BB*NN*NN];
__device__ __half g_s2_de_h[(size_t)BB*NN*NN];
__device__ float  g_ne[BN*EMB];
__device__ float  g_go[BN];
__device__ float  g_xf1[BN*24];
__device__ float  g_xf2[BN*24];
__device__ float  g_yf1[BN*TT];
__device__ float  g_yf2[BN*TT];
// transposed fp16 weights: [n][208]
__device__ __half g_WgeT[128*208];
__device__ __half g_WgdT[128*208];
__device__ __half g_WueT[64*208];
__device__ __half g_WudT[64*208];

__device__ __forceinline__ int wmap(int c) {
    if (c < 64)  return c + 2;
    if (c < 128) return c + 4;
    if (c < 192) return c + 6;
    return ((c - 192) >> 1) * 66 + (c & 1);
}

// ---------------- mma helpers ----------------
__device__ __forceinline__ unsigned f2tf(float f) {
    unsigned u;
    asm("cvt.rna.tf32.f32 %0, %1;" : "=r"(u) : "f"(f));
    return u;
}
__device__ __forceinline__ void mma_tf32(float* d,
    unsigned a0, unsigned a1, unsigned a2, unsigned a3,
    unsigned b0, unsigned b1) {
    asm volatile(
        "mma.sync.aligned.m16n8k8.row.col.f32.tf32.tf32.f32 "
        "{%0,%1,%2,%3}, {%4,%5,%6,%7}, {%8,%9}, {%0,%1,%2,%3};\n"
        : "+f"(d[0]), "+f"(d[1]), "+f"(d[2]), "+f"(d[3])
        : "r"(a0), "r"(a1), "r"(a2), "r"(a3), "r"(b0), "r"(b1));
}
__device__ __forceinline__ void mma_f16(float* d,
    unsigned a0, unsigned a1, unsigned a2, unsigned a3,
    unsigned b0, unsigned b1) {
    asm volatile(
        "mma.sync.aligned.m16n8k16.row.col.f32.f16.f16.f32 "
        "{%0,%1,%2,%3}, {%4,%5,%6,%7}, {%8,%9}, {%0,%1,%2,%3};\n"
        : "+f"(d[0]), "+f"(d[1]), "+f"(d[2]), "+f"(d[3])
        : "r"(a0), "r"(a1), "r"(a2), "r"(a3), "r"(b0), "r"(b1));
}
__device__ __forceinline__ void ldsm_x4(unsigned& r0, unsigned& r1,
                                        unsigned& r2, unsigned& r3, unsigned addr) {
    asm volatile("ldmatrix.sync.aligned.m8n8.x4.shared.b16 {%0,%1,%2,%3}, [%4];"
        : "=r"(r0), "=r"(r1), "=r"(r2), "=r"(r3) : "r"(addr));
}

__device__ __forceinline__ void cpa16(void* smem, const void* g) {
    unsigned s = (unsigned)__cvta_generic_to_shared(smem);
    asm volatile("cp.async.cg.shared.global [%0], [%1], 16;\n" :: "r"(s), "l"(g));
}
#define CP_COMMIT() asm volatile("cp.async.commit_group;\n" ::: "memory")
#define CP_WAIT1()  asm volatile("cp.async.wait_group 1;\n" ::: "memory")
#define CP_WAIT0()  asm volatile("cp.async.wait_group 0;\n" ::: "memory")

// ---------------- init ----------------
__global__ void k_zero() {
    size_t i = (size_t)blockIdx.x*blockDim.x + threadIdx.x;
    size_t st = (size_t)gridDim.x*blockDim.x;
    const __half hz = __float2half(0.f);
    for (size_t j=i; j<(size_t)BN*64; j+=st) { g_x0[j] = hz; g_x0T[j] = hz; }
    for (size_t j=i; j<BN*HID; j+=st) g_h[j]  = 0.f;
    for (size_t j=i; j<BN;     j+=st) g_go[j] = 0.f;
}

// ---------------- weight reorder (transposed fp16) --------------------------
__global__ void k_prep(const float* __restrict__ W, int which) {
    int nc = (which < 2) ? 128 : 64;
    __half* dst = (which == 0) ? g_WgeT : (which == 1) ? g_WgdT
               : (which == 2) ? g_WueT : g_WudT;
    int idx = blockIdx.x*blockDim.x + threadIdx.x;
    if (idx >= 208*nc) return;
    int c = idx / nc, o = idx - c*nc;
    float v = 0.f;
    if (c < 198) v = W[wmap(c)*nc + o];
    dst[(size_t)o*208 + c] = __float2half(v);
}

// ---------------- supports (fp32 + fp16 copies) ----------------
__global__ void k_support_en(const float* __restrict__ emb) {
    int n = blockIdx.x, tid = threadIdx.x;
    __shared__ float embn[EMB];
    __shared__ float row[NN];
    __shared__ float red[256];
    if (tid < EMB) embn[tid] = emb[n*EMB + tid];
    __syncthreads();
    for (int m=tid; m<NN; m+=256) {
        float s = 0.f;
        #pragma unroll
        for (int e=0; e<EMB; e++) s += embn[e]*emb[m*EMB+e];
        row[m] = fmaxf(s, 0.f);
    }
    __syncthreads();
    float lm = -1e30f;
    for (int m=tid; m<NN; m+=256) lm = fmaxf(lm, row[m]);
    red[tid]=lm; __syncthreads();
    for (int s=128;s>0;s>>=1){ if(tid<s) red[tid]=fmaxf(red[tid],red[tid+s]); __syncthreads(); }
    float mx = red[0]; __syncthreads();
    float ls = 0.f;
    for (int m=tid; m<NN; m+=256){ float e=expf(row[m]-mx); row[m]=e; ls+=e; }
    red[tid]=ls; __syncthreads();
    for (int s=128;s>0;s>>=1){ if(tid<s) red[tid]+=red[tid+s]; __syncthreads(); }
    float inv = 1.f/red[0];
    for (int m=tid; m<NN; m+=256) {
        float v = row[m]*inv;
        g_sup_en_f[n*NN+m] = v;
        g_sup_en_h[n*NN+m] = __float2half(v);
    }
}

__global__ void k_support_de() {
    int bn = blockIdx.x;
    int b = bn >> 9, n = bn & 511;
    int tid = threadIdx.x;
    const float* neb = g_ne + (size_t)b*NN*EMB;
    __shared__ float embn[EMB];
    __shared__ float row[NN];
    __shared__ float red[256];
    if (tid < EMB) embn[tid] = neb[n*EMB + tid];
    __syncthreads();
    for (int m=tid; m<NN; m+=256) {
        float s = 0.f;
        #pragma unroll
        for (int e=0; e<EMB; e++) s += embn[e]*neb[m*EMB+e];
        row[m] = fmaxf(s, 0.f);
    }
    __syncthreads();
    float lm = -1e30f;
    for (int m=tid; m<NN; m+=256) lm = fmaxf(lm, row[m]);
    red[tid]=lm; __syncthreads();
    for (int s=128;s>0;s>>=1){ if(tid<s) red[tid]=fmaxf(red[tid],red[tid+s]); __syncthreads(); }
    float mx = red[0]; __syncthreads();
    float ls = 0.f;
    for (int m=tid; m<NN; m+=256){ float e=expf(row[m]-mx); row[m]=e; ls+=e; }
    red[tid]=ls; __syncthreads();
    for (int s=128;s>0;s>>=1){ if(tid<s) red[tid]+=red[tid+s]; __syncthreads(); }
    float inv = 1.f/red[0];
    size_t base = (size_t)b*NN*NN + (size_t)n*NN;
    for (int m=tid; m<NN; m+=256) {
        float v = row[m]*inv;
        g_sup_de_f[base+m] = v;
        g_sup_de_h[base+m] = __float2half(v);
    }
}

// ---------------- S2 = S @ S  (tf32 MMA on fp32 S; dual-format output) ------
__global__ void __launch_bounds__(256) k_sq(int deFlag) {
    __shared__ float As[3][128*20];
    __shared__ float Bs[3][16*72];
    const int b  = blockIdx.z;
    const int m0 = blockIdx.x*128;
    const int n0 = blockIdx.y*64;
    const int tid = threadIdx.x;
    const int warp = tid >> 5, lane = tid & 31;
    const int mw = warp & 3, nw = warp >> 2;
    const int tq = lane >> 2, tr = lane & 3;
    const float* S = deFlag ? g_sup_de_f + (size_t)b*NN*NN : g_sup_en_f;
    float*  Df = deFlag ? g_s2_de_f + (size_t)b*NN*NN : g_s2_en_f;
    __half* Dh = deFlag ? g_s2_de_h + (size_t)b*NN*NN : g_s2_en_h;
    const int lr = tid >> 1, lc = (tid & 1)*8;
    const int bk = tid >> 4, bn = (tid & 15)*4;

    float acc[2][4][4] = {};

#define SQ_LOAD(st, k0) do { \
    cpa16(&As[st][lr*20+lc],   &S[(size_t)(m0+lr)*NN + (k0)+lc]); \
    cpa16(&As[st][lr*20+lc+4], &S[(size_t)(m0+lr)*NN + (k0)+lc+4]); \
    cpa16(&Bs[st][bk*72+bn],   &S[(size_t)((k0)+bk)*NN + n0 + bn]); \
} while(0)

    SQ_LOAD(0, 0);  CP_COMMIT();
    SQ_LOAD(1, 16); CP_COMMIT();
    for (int kt = 0; kt < 32; kt++) {
        CP_WAIT1();
        __syncthreads();
        if (kt < 30) SQ_LOAD((kt+2)%3, (kt+2)*16);
        CP_COMMIT();
        const float* Ab = As[kt%3];
        const float* Bb = Bs[kt%3];
        #pragma unroll
        for (int ks = 0; ks < 16; ks += 8) {
            unsigned a[2][4], bb[4][2];
            #pragma unroll
            for (int mi = 0; mi < 2; mi++) {
                int r = mw*32 + mi*16 + tq;
                a[mi][0] = f2tf(Ab[r*20 + ks + tr]);
                a[mi][1] = f2tf(Ab[(r+8)*20 + ks + tr]);
                a[mi][2] = f2tf(Ab[r*20 + ks + tr + 4]);
                a[mi][3] = f2tf(Ab[(r+8)*20 + ks + tr + 4]);
            }
            #pragma unroll
            for (int nj = 0; nj < 4; nj++) {
                int c = nw*32 + nj*8 + tq;
                bb[nj][0] = f2tf(Bb[(ks+tr)*72 + c]);
                bb[nj][1] = f2tf(Bb[(ks+tr+4)*72 + c]);
            }
            #pragma unroll
            for (int mi = 0; mi < 2; mi++)
                #pragma unroll
                for (int nj = 0; nj < 4; nj++)
                    mma_tf32(acc[mi][nj], a[mi][0], a[mi][1], a[mi][2], a[mi][3],
                             bb[nj][0], bb[nj][1]);
        }
    }
    __syncthreads();
    #pragma unroll
    for (int mi = 0; mi < 2; mi++) {
        int r0 = m0 + mw*32 + mi*16 + tq;
        #pragma unroll
        for (int nj = 0; nj < 4; nj++) {
            int c = n0 + nw*32 + nj*8 + tr*2;
            #pragma unroll
            for (int hh = 0; hh < 2; hh++) {
                int rr = r0 + hh*8;
                float va = acc[mi][nj][hh*2], vb = acc[mi][nj][hh*2+1];
                *(float2*)&Df[(size_t)rr*NN + c] = make_float2(va, vb);
                *(__half2*)&Dh[(size_t)rr*NN + c] = __floats2half2_rn(va, vb);
            }
        }
    }
#undef SQ_LOAD
}

// ---------------- x/ycov feature precompute ---------------------------------
__global__ void __launch_bounds__(256) k_pre_enc(const float* __restrict__ x) {
    __shared__ float xsh[512*24];
    int b = blockIdx.y, m0 = blockIdx.x*32, z = blockIdx.z;
    int tid = threadIdx.x;
    for (int idx = tid; idx < 512*24; idx += 256) {
        int k = idx/24, tc = idx%24;
        int t = tc>>1, c = tc&1;
        xsh[idx] = x[(((size_t)b*TT+t)*NN + k)*2 + c];
    }
    __syncthreads();
    int rl = tid>>3, kh = (tid>>2)&1, cg = tid&3;
    int row = m0 + rl, g = cg*6;
    float acc[6] = {};
    const float* Srow = (z ? g_s2_en_f : g_sup_en_f) + (size_t)row*NN + kh*256;
    const float* xp = &xsh[kh*256*24];
    for (int k=0;k<256;k+=4){
        float4 s = *(const float4*)&Srow[k];
        #pragma unroll
        for (int j=0;j<6;j++)
            acc[j] += s.x*xp[(k+0)*24+g+j] + s.y*xp[(k+1)*24+g+j]
                    + s.z*xp[(k+2)*24+g+j] + s.w*xp[(k+3)*24+g+j];
    }
    #pragma unroll
    for (int j=0;j<6;j++) acc[j] += __shfl_xor_sync(0xffffffffu, acc[j], 4);
    if (kh == 0) {
        #pragma unroll
        for (int j=0;j<6;j++) {
            int col = g + j;
            if (z == 0) g_xf1[((size_t)b*NN + row)*24 + col] = acc[j];
            else {
                int t = col>>1, c = col&1;
                g_xf2[((size_t)b*NN + row)*24 + col] =
                    2.f*acc[j] - x[(((size_t)b*TT+t)*NN + row)*2 + c];
            }
        }
    }
}

__global__ void __launch_bounds__(256) k_pre_dec(const float* __restrict__ ycov) {
    __shared__ float ysh[512*12];
    int b = blockIdx.y, m0 = blockIdx.x*32, z = blockIdx.z;
    int tid = threadIdx.x;
    for (int idx = tid; idx < 512*12; idx += 256) {
        int k = idx/12, t = idx%12;
        ysh[idx] = ycov[((size_t)b*TT+t)*NN + k];
    }
    __syncthreads();
    int rl = tid>>3, kh = (tid>>2)&1, cg = tid&3;
    int row = m0 + rl, g = cg*3;
    float acc[3] = {};
    const float* Srow = (z ? g_s2_de_f : g_sup_de_f)
                        + (size_t)b*NN*NN + (size_t)row*NN + kh*256;
    const float* yp = &ysh[kh*256*12];
    for (int k=0;k<256;k+=4){
        float4 s = *(const float4*)&Srow[k];
        #pragma unroll
        for (int j=0;j<3;j++)
            acc[j] += s.x*yp[(k+0)*12+g+j] + s.y*yp[(k+1)*12+g+j]
                    + s.z*yp[(k+2)*12+g+j] + s.w*yp[(k+3)*12+g+j];
    }
    #pragma unroll
    for (int j=0;j<3;j++) acc[j] += __shfl_xor_sync(0xffffffffu, acc[j], 4);
    if (kh == 0) {
        #pragma unroll
        for (int j=0;j<3;j++) {
            int t = g + j;
            if (z == 0) g_yf1[((size_t)b*NN + row)*12 + t] = acc[j];
            else        g_yf2[((size_t)b*NN + row)*12 + t] =
                            2.f*acc[j] - ycov[((size_t)b*TT+t)*NN + row];
        }
    }
}

// ---------------- fused cell-phase kernel (M-tile 64, 2 CTAs/SM) -------------
__global__ void __launch_bounds__(256) k_cell(
    int phase, int deFlag, int t,
    const float* __restrict__ x, const float* __restrict__ ycov,
    const float* __restrict__ bias,
    const float* __restrict__ pW, const float* __restrict__ pb,
    float* __restrict__ out)
{
    extern __shared__ char smx[];
    __half* PAN = (__half*)(smx + OFF_PAN);
    __half* SS  = (__half*)(smx + OFF_SS);
    __half* S2S = (__half*)(smx + OFF_S2);
    __half* XB  = (__half*)(smx + OFF_XB);
    float*  GOs = (float*)(smx + OFF_GO);
    __shared__ float pr[2][64];

    const int b  = blockIdx.y;
    const int m0 = blockIdx.x*64;
    const int tid = threadIdx.x;
    const int warp = tid >> 5, lane = tid & 31;
    const int mw = warp & 3, nw = warp >> 2;
    const int tq = lane >> 2, tr = lane & 3;

    // ldmatrix lane geometry
    const int l8 = lane & 7, mt = lane >> 3;
    const int arow = l8 + (mt & 1)*8;
    const int acol = (mt >> 1)*8;
    const int brow = l8 + (mt >> 1)*8;
    const int bcol = (mt & 1)*8;
    const unsigned aOff  = ((mw*16 + arow)*24 + acol)*2;   // warp m16 block
    const unsigned bOff0 = ((nw*32 + brow)*24 + bcol)*2;
    const unsigned bOff1 = bOff0 + 16*48;
    const unsigned uPAN = (unsigned)__cvta_generic_to_shared(PAN);
    const unsigned uSS  = (unsigned)__cvta_generic_to_shared(SS);
    const unsigned uS2  = (unsigned)__cvta_generic_to_shared(S2S);
    const unsigned uXB  = (unsigned)__cvta_generic_to_shared(XB);

    const __half* Sh  = deFlag ? g_sup_de_h + (size_t)b*NN*NN : g_sup_en_h;
    const __half* S2h = deFlag ? g_s2_de_h  + (size_t)b*NN*NN : g_s2_en_h;
    const __half* Xrow = (phase == 0) ? g_x0 : g_x1;
    const __half* XT   = (phase == 0) ? g_x0T : g_x1T;

    // ---- preload panel tiles 0..3 (X own 64 rows): 512 chunks, 2/thread ----
    #pragma unroll
    for (int i = 0; i < 2; i++) {
        int ch = tid + i*256;
        int tI = ch >> 7, rw = (ch >> 1) & 63, off = (ch & 1)*8;
        cpa16(&PAN[tI*TILEH + rw*24 + off],
              &Xrow[((size_t)b*NN + m0 + rw)*64 + tI*16 + off]);
    }
    if (deFlag) {
        GOs[tid]       = g_go[(size_t)b*NN + tid];
        GOs[tid + 256] = g_go[(size_t)b*NN + tid + 256];
    }
    CP_COMMIT();

    // ---- phase A: Y1 = S@X, Y2raw = S2@X (K=512, 32 k16-tiles) ----
    float acc1[4][4] = {};
    float acc2[4][4] = {};
    float d1 = 0.f, d2 = 0.f;
    const int mvrow = tid >> 2, mvh = (tid & 3)*4;

#define PA_LOAD(st, k0) do { \
    if (tid < 128) { \
        int r_ = tid >> 1, o_ = (tid & 1)*8; \
        cpa16(&SS[(st)*TILEH + r_*24 + o_], &Sh[(size_t)(m0+r_)*NN + (k0)+o_]); \
        cpa16(&XB[(st)*TILEH + r_*24 + o_], &XT[((size_t)b*64 + r_)*NN + (k0)+o_]); \
    } else { \
        int r_ = (tid-128) >> 1, o_ = (tid & 1)*8; \
        cpa16(&S2S[(st)*TILEH + r_*24 + o_], &S2h[(size_t)(m0+r_)*NN + (k0)+o_]); \
    } \
} while(0)

    PA_LOAD(0, 0);  CP_COMMIT();
    PA_LOAD(1, 16); CP_COMMIT();
    for (int kt = 0; kt < 32; kt++) {
        CP_WAIT1();
        __syncthreads();
        if (kt < 30) PA_LOAD((kt+2)%3, (kt+2)*16);
        CP_COMMIT();
        const unsigned sb  = uSS + (kt%3)*TILEB;
        const unsigned s2b = uS2 + (kt%3)*TILEB;
        const unsigned xb  = uXB + (kt%3)*TILEB;
        unsigned a[4], a2[4], bb[4][2];
        ldsm_x4(a [0], a [1], a [2], a [3], sb  + aOff);
        ldsm_x4(a2[0], a2[1], a2[2], a2[3], s2b + aOff);
        ldsm_x4(bb[0][0], bb[0][1], bb[1][0], bb[1][1], xb + bOff0);
        ldsm_x4(bb[2][0], bb[2][1], bb[3][0], bb[3][1], xb + bOff1);
        #pragma unroll
        for (int nj = 0; nj < 4; nj++) {
            mma_f16(acc1[nj], a [0], a [1], a [2], a [3], bb[nj][0], bb[nj][1]);
            mma_f16(acc2[nj], a2[0], a2[1], a2[2], a2[3], bb[nj][0], bb[nj][1]);
        }
        if (deFlag) {
            const __half* Ab  = SS  + (kt%3)*TILEH;
            const __half* A2b = S2S + (kt%3)*TILEH;
            const __half2* ap  = (const __half2*)&Ab [mvrow*24 + mvh];
            const __half2* a2p = (const __half2*)&A2b[mvrow*24 + mvh];
            const float* gop = &GOs[kt*16 + mvh];
            #pragma unroll
            for (int j = 0; j < 2; j++) {
                float2 v  = __half22float2(ap[j]);
                float2 v2 = __half22float2(a2p[j]);
                d1 += v.x*gop[2*j] + v.y*gop[2*j+1];
                d2 += v2.x*gop[2*j] + v2.y*gop[2*j+1];
            }
        }
    }
    CP_WAIT0();
    __syncthreads();

    // ---- write Y1 (tiles 4..7), Y2 = 2*acc2 - X (tiles 8..11) ----
    {
        int r = mw*16 + tq;
        #pragma unroll
        for (int nj = 0; nj < 4; nj++) {
            int c = nw*32 + nj*8 + tr*2;
            int tI = c >> 4, kk = c & 15;
            #pragma unroll
            for (int hh = 0; hh < 2; hh++) {
                int rr = r + hh*8;
                float v1a = acc1[nj][hh*2], v1b = acc1[nj][hh*2+1];
                float v2a = acc2[nj][hh*2], v2b = acc2[nj][hh*2+1];
                float xa  = __half2float(PAN[tI*TILEH + rr*24 + kk]);
                float xb2 = __half2float(PAN[tI*TILEH + rr*24 + kk + 1]);
                *(__half2*)&PAN[(4+tI)*TILEH + rr*24 + kk] =
                    __floats2half2_rn(v1a, v1b);
                *(__half2*)&PAN[(8+tI)*TILEH + rr*24 + kk] =
                    __floats2half2_rn(2.f*v2a - xa, 2.f*v2b - xb2);
            }
        }
    }

    // ---- tile 12: extra features (rows 0..63) ----
    if (deFlag) {
        d1 += __shfl_xor_sync(0xffffffffu, d1, 1);
        d1 += __shfl_xor_sync(0xffffffffu, d1, 2);
        d2 += __shfl_xor_sync(0xffffffffu, d2, 1);
        d2 += __shfl_xor_sync(0xffffffffu, d2, 2);
        if ((tid & 3) == 0) {
            int rw = tid >> 2;
            size_t gr = (size_t)b*NN + m0 + rw;
            float go = GOs[m0 + rw];
            __half* T = &PAN[12*TILEH + rw*24];
            T[0] = __float2half(go);
            T[1] = __float2half(ycov[((size_t)b*TT + t)*NN + m0 + rw]);
            T[2] = __float2half(d1);
            T[3] = __float2half(g_yf1[gr*12 + t]);
            T[4] = __float2half(2.f*d2 - go);
            T[5] = __float2half(g_yf2[gr*12 + t]);
            #pragma unroll
            for (int j = 6; j < 16; j++) T[j] = __float2half(0.f);
        }
    } else {
        if (tid < 64) {
            int rw = tid;
            size_t gr = (size_t)b*NN + m0 + rw;
            const float* xp = &x[(((size_t)b*TT + t)*NN + m0 + rw)*2];
            __half* T = &PAN[12*TILEH + rw*24];
            T[0] = __float2half(xp[0]);
            T[1] = __float2half(xp[1]);
            T[2] = __float2half(g_xf1[gr*24 + t*2 + 0]);
            T[3] = __float2half(g_xf1[gr*24 + t*2 + 1]);
            T[4] = __float2half(g_xf2[gr*24 + t*2 + 0]);
            T[5] = __float2half(g_xf2[gr*24 + t*2 + 1]);
            #pragma unroll
            for (int j = 6; j < 16; j++) T[j] = __float2half(0.f);
        }
    }
    __syncthreads();

    // ---- phase B: weight GEMM over K=208 from the panel ----
    if (phase == 0) {
        // gate: N=128. W staging spans SS+S2S regions: 3 stages x 6144 B.
        const __half* WT = deFlag ? g_WgdT : g_WgeT;
        float acc[8][4] = {};
        const unsigned bG0 = ((nw*64 + brow)*24 + bcol)*2;
#define WB_LOAD128(st, k0) do { \
    int n_ = tid >> 1, of_ = (tid & 1)*8; \
    cpa16(&SS[(st)*3072 + n_*24 + of_], &WT[(size_t)n_*208 + (k0)+of_]); \
} while(0)
        WB_LOAD128(0, 0);  CP_COMMIT();
        WB_LOAD128(1, 16); CP_COMMIT();
        for (int kt = 0; kt < 13; kt++) {
            CP_WAIT1();
            __syncthreads();
            if (kt < 11) WB_LOAD128((kt+2)%3, (kt+2)*16);
            CP_COMMIT();
            const unsigned pb_ = uPAN + kt*TILEB;
            const unsigned wb  = uSS + (kt%3)*6144;
            unsigned a[4], bb[8][2];
            ldsm_x4(a[0], a[1], a[2], a[3], pb_ + aOff);
            #pragma unroll
            for (int j = 0; j < 4; j++)
                ldsm_x4(bb[2*j][0], bb[2*j][1], bb[2*j+1][0], bb[2*j+1][1],
                        wb + bG0 + j*16*48);
            #pragma unroll
            for (int nj = 0; nj < 8; nj++)
                mma_f16(acc[nj], a[0], a[1], a[2], a[3], bb[nj][0], bb[nj][1]);
        }
        {
            int r0 = mw*16 + tq;
            #pragma unroll
            for (int nj = 0; nj < 8; nj++) {
                int c = nw*64 + nj*8 + tr*2;
                #pragma unroll
                for (int hh = 0; hh < 2; hh++) {
                    int ln = m0 + r0 + hh*8;
                    size_t row = (size_t)b*NN + ln;
                    float va = acc[nj][hh*2], vb = acc[nj][hh*2+1];
                    float za = 1.f/(1.f + expf(-(va + bias[c])));
                    float zb = 1.f/(1.f + expf(-(vb + bias[c+1])));
                    if (c < 64) {
                        float ha = za * g_h[row*HID + c];
                        float hb = zb * g_h[row*HID + c+1];
                        *(__half2*)&g_x1[row*64 + c] = __floats2half2_rn(ha, hb);
                        g_x1T[((size_t)b*64 + c  )*NN + ln] = __float2half(ha);
                        g_x1T[((size_t)b*64 + c+1)*NN + ln] = __float2half(hb);
                    } else {
                        g_r[row*HID + (c-64)]   = za;
                        g_r[row*HID + (c-64)+1] = zb;
                    }
                }
            }
        }
#undef WB_LOAD128
    } else {
        const __half* WT = deFlag ? g_WudT : g_WueT;
        float acc[4][4] = {};
#define WB_LOAD64(st, k0) do { \
    if (tid < 128) { int n_ = tid >> 1, of_ = (tid & 1)*8; \
        cpa16(&SS[(st)*TILEH + n_*24 + of_], &WT[(size_t)n_*208 + (k0)+of_]); } \
} while(0)
        WB_LOAD64(0, 0);  CP_COMMIT();
        WB_LOAD64(1, 16); CP_COMMIT();
        for (int kt = 0; kt < 13; kt++) {
            CP_WAIT1();
            __syncthreads();
            if (kt < 11) WB_LOAD64((kt+2)%3, (kt+2)*16);
            CP_COMMIT();
            const unsigned pb_ = uPAN + kt*TILEB;
            const unsigned wb  = uSS + (kt%3)*TILEB;
            unsigned a[4], bb[4][2];
            ldsm_x4(a[0], a[1], a[2], a[3], pb_ + aOff);
            ldsm_x4(bb[0][0], bb[0][1], bb[1][0], bb[1][1], wb + bOff0);
            ldsm_x4(bb[2][0], bb[2][1], bb[3][0], bb[3][1], wb + bOff1);
            #pragma unroll
            for (int nj = 0; nj < 4; nj++)
                mma_f16(acc[nj], a[0], a[1], a[2], a[3], bb[nj][0], bb[nj][1]);
        }
        const bool doProj = (deFlag != 0);
        float rowsum[2] = {};
        {
            int r0 = mw*16 + tq;
            #pragma unroll
            for (int nj = 0; nj < 4; nj++) {
                int c = nw*32 + nj*8 + tr*2;
                #pragma unroll
                for (int hh = 0; hh < 2; hh++) {
                    int ln = m0 + r0 + hh*8;
                    size_t row = (size_t)b*NN + ln;
                    float hn2[2];
                    #pragma unroll
                    for (int jj = 0; jj < 2; jj++) {
                        int o = c + jj;
                        float hc = tanhf(acc[nj][hh*2+jj] + bias[o]);
                        float r  = g_r[row*HID + o];
                        float h  = g_h[row*HID + o];
                        float hn = r*h + (1.f - r)*hc;
                        g_h[row*HID + o] = hn;
                        g_x0T[((size_t)b*64 + o)*NN + ln] = __float2half(hn);
                        hn2[jj] = hn;
                        if (doProj) rowsum[hh] += hn * pW[o];
                    }
                    *(__half2*)&g_x0[row*64 + c] = __floats2half2_rn(hn2[0], hn2[1]);
                }
            }
        }
        if (doProj) {
            #pragma unroll
            for (int hh = 0; hh < 2; hh++) {
                float v = rowsum[hh];
                v += __shfl_xor_sync(0xffffffffu, v, 1);
                v += __shfl_xor_sync(0xffffffffu, v, 2);
                if (tr == 0) pr[nw][mw*16 + tq + hh*8] = v;
            }
            __syncthreads();
            if (tid < 64) {
                int n = m0 + tid;
                float go = pr[0][tid] + pr[1][tid] + pb[0];
                g_go[(size_t)b*NN + n] = go;
                out[((size_t)b*TT + t)*NN + n] = go;
            }
        }
#undef WB_LOAD64
    }
#undef PA_LOAD
}

// ---------------- hyper projection ------------------------------------------
__global__ void k_hyper(const float* __restrict__ hW, const float* __restrict__ hb) {
    int idx = blockIdx.x*blockDim.x + threadIdx.x;
    if (idx >= BN*EMB) return;
    int bn = idx / EMB, e = idx % EMB;
    float s = hb[e];
    #pragma unroll
    for (int k = 0; k < HID; k++) s += g_h[(size_t)bn*HID + k] * hW[k*EMB + e];
    g_ne[idx] = s;
}

// ---------------- orchestration ---------------------------------------------
extern "C" void kernel_launch(void* const* d_in, const int* in_sizes, int n_in,
                              void* d_out, int out_size) {
    const float* x       = (const float*)d_in[0];
    const float* ycov    = (const float*)d_in[1];
    const float* emb     = (const float*)d_in[2];
    const float* enc_gW  = (const float*)d_in[3];
    const float* enc_gb  = (const float*)d_in[4];
    const float* enc_uW  = (const float*)d_in[5];
    const float* enc_ub  = (const float*)d_in[6];
    const float* dec_gW  = (const float*)d_in[7];
    const float* dec_gb  = (const float*)d_in[8];
    const float* dec_uW  = (const float*)d_in[9];
    const float* dec_ub  = (const float*)d_in[10];
    const float* proj_W  = (const float*)d_in[11];
    const float* proj_b  = (const float*)d_in[12];
    const float* hyper_W = (const float*)d_in[13];
    const float* hyper_b = (const float*)d_in[14];
    float* out = (float*)d_out;

    static int smem_set = 0;
    if (!smem_set) {
        cudaFuncSetAttribute(k_cell, cudaFuncAttributeMaxDynamicSharedMemorySize,
                             SM_BYTES);
        smem_set = 1;
    }

    dim3 gs_cell(8, BB);       // 256 CTAs, 2 per SM
    dim3 gs_sq_en(4, 8, 1);
    dim3 gs_sq_de(4, 8, BB);
    dim3 gs_pre(16, BB, 2);

    k_zero<<<1024, 256>>>();
    k_prep<<<(208*128+255)/256, 256>>>(enc_gW, 0);
    k_prep<<<(208*128+255)/256, 256>>>(dec_gW, 1);
    k_prep<<<(208*64+255)/256, 256>>>(enc_uW, 2);
    k_prep<<<(208*64+255)/256, 256>>>(dec_uW, 3);
    k_support_en<<<NN, 256>>>(emb);
    k_sq<<<gs_sq_en, 256>>>(0);
    k_pre_enc<<<gs_pre, 256>>>(x);

    for (int t = 0; t < TT; t++) {
        k_cell<<<gs_cell, 256, SM_BYTES>>>(0, 0, t, x, ycov, enc_gb,
                                           nullptr, nullptr, nullptr);
        k_cell<<<gs_cell, 256, SM_BYTES>>>(1, 0, t, x, ycov, enc_ub,
                                           nullptr, nullptr, nullptr);
    }

    k_hyper<<<(BN*EMB + 255)/256, 256>>>(hyper_W, hyper_b);
    k_support_de<<<BN, 256>>>();
    k_sq<<<gs_sq_de, 256>>>(1);
    k_pre_dec<<<gs_pre, 256>>>(ycov);

    for (int t = 0; t < TT; t++) {
        k_cell<<<gs_cell, 256, SM_BYTES>>>(0, 1, t, x, ycov, dec_gb,
                                           nullptr, nullptr, nullptr);
        k_cell<<<gs_cell, 256, SM_BYTES>>>(1, 1, t, x, ycov, dec_ub,
                                           proj_W, proj_b, out);
    }
}

// round 15
// speedup vs baseline: 1.0738x; 1.0407x over previous
#include <cuda_runtime.h>
#include <cuda_fp16.h>
#include <math.h>

// ---------------- problem constants ----------------
#define BB   32
#define TT   12
#define NN   512
#define HID  64
#define EMB  10
#define BN   (BB*NN)     // 16384

// Feature K layout for the weight GEMM (208 rows), weights FOLDED:
//  0..63   X (h or z*h)      <- Wx - Wy2
//  64..127 S@X               <- W1
//  128..191 S^2@X            <- 2*Wy2
//  192..197 [x0,x1,Sx0,Sx1,S2x0,S2x1] (orig rows 0,1,66,67,132,133)
//  198..207 zero pad

// ---------------- dynamic smem layout (bytes) ----------------
#define TILEH   3072        // halves per 128x24 tile
#define TILEB   6144
#define OFF_PAN 0           // 13 tiles       -> 79872
#define OFF_SS  79872       // 3 stages S     -> 18432
#define OFF_S2  98304       // 3 stages S2    -> 18432
#define OFF_XB  116736      // 3 stages 64x24 -> 9216
#define OFF_GO  125952      // 512 floats     -> 2048
#define SM_BYTES 128000

// ---------------- device scratch ----------------
__device__ float  g_h[BN*HID];
__device__ float  g_r[BN*HID];
__device__ __half g_x0 [BN*64];          // h, row-major
__device__ __half g_x0T[BB*64*NN];       // h, [b][c][n]
__device__ __half g_x1 [BN*64];          // z*h, row-major
__device__ __half g_x1T[BB*64*NN];
__device__ float  g_sup_en_f[NN*NN];
__device__ __half g_sup_en_h[NN*NN];
__device__ __half g_supT_en[NN*NN];      // S^T fp16
__device__ float  g_sup_de_f[(size_t)BB*NN*NN];
__device__ __half g_sup_de_h[(size_t)BB*NN*NN];
__device__ __half g_supT_de[(size_t)BB*NN*NN];
__device__ float  g_s2_en_f[NN*NN];
__device__ __half g_s2_en_h[NN*NN];
__device__ float  g_s2_de_f[(size_t)BB*NN*NN];
__device__ __half g_s2_de_h[(size_t)BB*NN*NN];
__device__ float  g_ne[BN*EMB];
__device__ float  g_go[BN];
__device__ float  g_xf1[BN*24];
__device__ float  g_xf2[BN*24];
__device__ float  g_yf1[BN*TT];
__device__ float  g_yf2[BN*TT];
// transposed fp16 weights: [n][208], FOLDED layout
__device__ __half g_WgeT[128*208];
__device__ __half g_WgdT[128*208];
__device__ __half g_WueT[64*208];
__device__ __half g_WudT[64*208];

// ---------------- mma helpers ----------------
__device__ __forceinline__ void mma_f16(float* d,
    unsigned a0, unsigned a1, unsigned a2, unsigned a3,
    unsigned b0, unsigned b1) {
    asm volatile(
        "mma.sync.aligned.m16n8k16.row.col.f32.f16.f16.f32 "
        "{%0,%1,%2,%3}, {%4,%5,%6,%7}, {%8,%9}, {%0,%1,%2,%3};\n"
        : "+f"(d[0]), "+f"(d[1]), "+f"(d[2]), "+f"(d[3])
        : "r"(a0), "r"(a1), "r"(a2), "r"(a3), "r"(b0), "r"(b1));
}
__device__ __forceinline__ void ldsm_x4(unsigned& r0, unsigned& r1,
                                        unsigned& r2, unsigned& r3, unsigned addr) {
    asm volatile("ldmatrix.sync.aligned.m8n8.x4.shared.b16 {%0,%1,%2,%3}, [%4];"
        : "=r"(r0), "=r"(r1), "=r"(r2), "=r"(r3) : "r"(addr));
}
__device__ __forceinline__ void cpa16(void* smem, const void* g) {
    unsigned s = (unsigned)__cvta_generic_to_shared(smem);
    asm volatile("cp.async.cg.shared.global [%0], [%1], 16;\n" :: "r"(s), "l"(g));
}
#define CP_COMMIT() asm volatile("cp.async.commit_group;\n" ::: "memory")
#define CP_WAIT1()  asm volatile("cp.async.wait_group 1;\n" ::: "memory")
#define CP_WAIT0()  asm volatile("cp.async.wait_group 0;\n" ::: "memory")

// ---------------- init ----------------
__global__ void k_zero() {
    size_t i = (size_t)blockIdx.x*blockDim.x + threadIdx.x;
    size_t st = (size_t)gridDim.x*blockDim.x;
    const __half hz = __float2half(0.f);
    for (size_t j=i; j<(size_t)BN*64; j+=st) { g_x0[j] = hz; g_x0T[j] = hz; }
    for (size_t j=i; j<BN*HID; j+=st) g_h[j]  = 0.f;
    for (size_t j=i; j<BN;     j+=st) g_go[j] = 0.f;
}

// ---------------- weight reorder (transposed fp16, FOLDED) ------------------
__global__ void k_prep(const float* __restrict__ W, int which) {
    int nc = (which < 2) ? 128 : 64;
    __half* dst = (which == 0) ? g_WgeT : (which == 1) ? g_WgdT
               : (which == 2) ? g_WueT : g_WudT;
    int idx = blockIdx.x*blockDim.x + threadIdx.x;
    if (idx >= 208*nc) return;
    int c = idx / nc, o = idx - c*nc;
    float v;
    if      (c < 64)  v = W[(c+2)*nc + o] - W[(c+134)*nc + o];   // Wx - Wy2
    else if (c < 128) v = W[(c+4)*nc + o];                        // W1
    else if (c < 192) v = 2.f * W[(c+6)*nc + o];                  // 2*Wy2
    else if (c < 198) v = W[(((c-192)>>1)*66 + (c&1))*nc + o];    // x-features
    else              v = 0.f;
    dst[(size_t)o*208 + c] = __float2half(v);
}

// ---------------- supports (fp32 + fp16 copies) ----------------
__global__ void k_support_en(const float* __restrict__ emb) {
    int n = blockIdx.x, tid = threadIdx.x;
    __shared__ float embn[EMB];
    __shared__ float row[NN];
    __shared__ float red[256];
    if (tid < EMB) embn[tid] = emb[n*EMB + tid];
    __syncthreads();
    for (int m=tid; m<NN; m+=256) {
        float s = 0.f;
        #pragma unroll
        for (int e=0; e<EMB; e++) s += embn[e]*emb[m*EMB+e];
        row[m] = fmaxf(s, 0.f);
    }
    __syncthreads();
    float lm = -1e30f;
    for (int m=tid; m<NN; m+=256) lm = fmaxf(lm, row[m]);
    red[tid]=lm; __syncthreads();
    for (int s=128;s>0;s>>=1){ if(tid<s) red[tid]=fmaxf(red[tid],red[tid+s]); __syncthreads(); }
    float mx = red[0]; __syncthreads();
    float ls = 0.f;
    for (int m=tid; m<NN; m+=256){ float e=expf(row[m]-mx); row[m]=e; ls+=e; }
    red[tid]=ls; __syncthreads();
    for (int s=128;s>0;s>>=1){ if(tid<s) red[tid]+=red[tid+s]; __syncthreads(); }
    float inv = 1.f/red[0];
    for (int m=tid; m<NN; m+=256) {
        float v = row[m]*inv;
        g_sup_en_f[n*NN+m] = v;
        g_sup_en_h[n*NN+m] = __float2half(v);
    }
}

__global__ void k_support_de() {
    int bn = blockIdx.x;
    int b = bn >> 9, n = bn & 511;
    int tid = threadIdx.x;
    const float* neb = g_ne + (size_t)b*NN*EMB;
    __shared__ float embn[EMB];
    __shared__ float row[NN];
    __shared__ float red[256];
    if (tid < EMB) embn[tid] = neb[n*EMB + tid];
    __syncthreads();
    for (int m=tid; m<NN; m+=256) {
        float s = 0.f;
        #pragma unroll
        for (int e=0; e<EMB; e++) s += embn[e]*neb[m*EMB+e];
        row[m] = fmaxf(s, 0.f);
    }
    __syncthreads();
    float lm = -1e30f;
    for (int m=tid; m<NN; m+=256) lm = fmaxf(lm, row[m]);
    red[tid]=lm; __syncthreads();
    for (int s=128;s>0;s>>=1){ if(tid<s) red[tid]=fmaxf(red[tid],red[tid+s]); __syncthreads(); }
    float mx = red[0]; __syncthreads();
    float ls = 0.f;
    for (int m=tid; m<NN; m+=256){ float e=expf(row[m]-mx); row[m]=e; ls+=e; }
    red[tid]=ls; __syncthreads();
    for (int s=128;s>0;s>>=1){ if(tid<s) red[tid]+=red[tid+s]; __syncthreads(); }
    float inv = 1.f/red[0];
    size_t base = (size_t)b*NN*NN + (size_t)n*NN;
    for (int m=tid; m<NN; m+=256) {
        float v = row[m]*inv;
        g_sup_de_f[base+m] = v;
        g_sup_de_h[base+m] = __float2half(v);
    }
}

// ---------------- support transpose (fp16): S^T[c][r] = S[r][c] -------------
__global__ void __launch_bounds__(256) k_tr(int deFlag) {
    __shared__ __half tile[64][72];
    int b = blockIdx.z;
    int r0 = blockIdx.y*64, c0 = blockIdx.x*64;
    const __half* src = deFlag ? g_sup_de_h + (size_t)b*NN*NN : g_sup_en_h;
    __half* dst = deFlag ? g_supT_de + (size_t)b*NN*NN : g_supT_en;
    int tid = threadIdx.x;
    #pragma unroll
    for (int i = 0; i < 8; i++) {
        int q = tid + i*256;
        int r = q >> 5, c2 = q & 31;
        __half2 v = *(const __half2*)&src[(size_t)(r0+r)*NN + c0 + c2*2];
        tile[r][c2*2]   = __low2half(v);
        tile[r][c2*2+1] = __high2half(v);
    }
    __syncthreads();
    #pragma unroll
    for (int i = 0; i < 8; i++) {
        int q = tid + i*256;
        int r = q >> 5, c2 = q & 31;
        __half2 v = __halves2half2(tile[c2*2][r], tile[c2*2+1][r]);
        *(__half2*)&dst[(size_t)(c0+r)*NN + r0 + c2*2] = v;
    }
}

// ---------------- S2 = S @ S  (fp16 MMA + ldmatrix; dual-format out) --------
__global__ void __launch_bounds__(256) k_sq(int deFlag) {
    __shared__ __half As[3][128*24];
    __shared__ __half Bs[3][64*24];
    const int b  = blockIdx.z;
    const int m0 = blockIdx.x*128;
    const int n0 = blockIdx.y*64;
    const int tid = threadIdx.x;
    const int warp = tid >> 5, lane = tid & 31;
    const int mw = warp & 3, nw = warp >> 2;
    const int tq = lane >> 2, tr = lane & 3;
    const int l8 = lane & 7, mt = lane >> 3;
    const int arow = l8 + (mt & 1)*8;
    const int acol = (mt >> 1)*8;
    const int brow = l8 + (mt >> 1)*8;
    const int bcol = (mt & 1)*8;
    const unsigned aOff0 = ((mw*32 + arow)*24 + acol)*2;
    const unsigned aOff1 = aOff0 + 16*48;
    const unsigned bOff0 = ((nw*32 + brow)*24 + bcol)*2;
    const unsigned bOff1 = bOff0 + 16*48;
    const unsigned uA = (unsigned)__cvta_generic_to_shared(As);
    const unsigned uB = (unsigned)__cvta_generic_to_shared(Bs);

    const __half* Sh = deFlag ? g_sup_de_h + (size_t)b*NN*NN : g_sup_en_h;
    const __half* ST = deFlag ? g_supT_de  + (size_t)b*NN*NN : g_supT_en;
    float*  Df = deFlag ? g_s2_de_f + (size_t)b*NN*NN : g_s2_en_f;
    __half* Dh = deFlag ? g_s2_de_h + (size_t)b*NN*NN : g_s2_en_h;

    float acc[2][4][4] = {};

#define SQ_LOAD(st, k0) do { \
    { int r_ = tid >> 1, o_ = (tid & 1)*8; \
      cpa16(&As[st][r_*24 + o_], &Sh[(size_t)(m0+r_)*NN + (k0)+o_]); } \
    if (tid < 128) { int r_ = tid >> 1, o_ = (tid & 1)*8; \
      cpa16(&Bs[st][r_*24 + o_], &ST[(size_t)(n0+r_)*NN + (k0)+o_]); } \
} while(0)

    SQ_LOAD(0, 0);  CP_COMMIT();
    SQ_LOAD(1, 16); CP_COMMIT();
    for (int kt = 0; kt < 32; kt++) {
        CP_WAIT1();
        __syncthreads();
        if (kt < 30) SQ_LOAD((kt+2)%3, (kt+2)*16);
        CP_COMMIT();
        const unsigned ab = uA + (kt%3)*(128*24*2);
        const unsigned bb_ = uB + (kt%3)*(64*24*2);
        unsigned a[2][4], bb[4][2];
        ldsm_x4(a[0][0], a[0][1], a[0][2], a[0][3], ab + aOff0);
        ldsm_x4(a[1][0], a[1][1], a[1][2], a[1][3], ab + aOff1);
        ldsm_x4(bb[0][0], bb[0][1], bb[1][0], bb[1][1], bb_ + bOff0);
        ldsm_x4(bb[2][0], bb[2][1], bb[3][0], bb[3][1], bb_ + bOff1);
        #pragma unroll
        for (int mi = 0; mi < 2; mi++)
            #pragma unroll
            for (int nj = 0; nj < 4; nj++)
                mma_f16(acc[mi][nj], a[mi][0], a[mi][1], a[mi][2], a[mi][3],
                        bb[nj][0], bb[nj][1]);
    }
    CP_WAIT0();
    __syncthreads();
    #pragma unroll
    for (int mi = 0; mi < 2; mi++) {
        int r0 = m0 + mw*32 + mi*16 + tq;
        #pragma unroll
        for (int nj = 0; nj < 4; nj++) {
            int c = n0 + nw*32 + nj*8 + tr*2;
            #pragma unroll
            for (int hh = 0; hh < 2; hh++) {
                int rr = r0 + hh*8;
                float va = acc[mi][nj][hh*2], vb = acc[mi][nj][hh*2+1];
                *(float2*)&Df[(size_t)rr*NN + c] = make_float2(va, vb);
                *(__half2*)&Dh[(size_t)rr*NN + c] = __floats2half2_rn(va, vb);
            }
        }
    }
#undef SQ_LOAD
}

// ---------------- x/ycov feature precompute ---------------------------------
__global__ void __launch_bounds__(256) k_pre_enc(const float* __restrict__ x) {
    __shared__ float xsh[512*24];
    int b = blockIdx.y, m0 = blockIdx.x*32, z = blockIdx.z;
    int tid = threadIdx.x;
    for (int idx = tid; idx < 512*24; idx += 256) {
        int k = idx/24, tc = idx%24;
        int t = tc>>1, c = tc&1;
        xsh[idx] = x[(((size_t)b*TT+t)*NN + k)*2 + c];
    }
    __syncthreads();
    int rl = tid>>3, kh = (tid>>2)&1, cg = tid&3;
    int row = m0 + rl, g = cg*6;
    float acc[6] = {};
    const float* Srow = (z ? g_s2_en_f : g_sup_en_f) + (size_t)row*NN + kh*256;
    const float* xp = &xsh[kh*256*24];
    for (int k=0;k<256;k+=4){
        float4 s = *(const float4*)&Srow[k];
        #pragma unroll
        for (int j=0;j<6;j++)
            acc[j] += s.x*xp[(k+0)*24+g+j] + s.y*xp[(k+1)*24+g+j]
                    + s.z*xp[(k+2)*24+g+j] + s.w*xp[(k+3)*24+g+j];
    }
    #pragma unroll
    for (int j=0;j<6;j++) acc[j] += __shfl_xor_sync(0xffffffffu, acc[j], 4);
    if (kh == 0) {
        #pragma unroll
        for (int j=0;j<6;j++) {
            int col = g + j;
            if (z == 0) g_xf1[((size_t)b*NN + row)*24 + col] = acc[j];
            else {
                int t = col>>1, c = col&1;
                g_xf2[((size_t)b*NN + row)*24 + col] =
                    2.f*acc[j] - x[(((size_t)b*TT+t)*NN + row)*2 + c];
            }
        }
    }
}

__global__ void __launch_bounds__(256) k_pre_dec(const float* __restrict__ ycov) {
    __shared__ float ysh[512*12];
    int b = blockIdx.y, m0 = blockIdx.x*32, z = blockIdx.z;
    int tid = threadIdx.x;
    for (int idx = tid; idx < 512*12; idx += 256) {
        int k = idx/12, t = idx%12;
        ysh[idx] = ycov[((size_t)b*TT+t)*NN + k];
    }
    __syncthreads();
    int rl = tid>>3, kh = (tid>>2)&1, cg = tid&3;
    int row = m0 + rl, g = cg*3;
    float acc[3] = {};
    const float* Srow = (z ? g_s2_de_f : g_sup_de_f)
                        + (size_t)b*NN*NN + (size_t)row*NN + kh*256;
    const float* yp = &ysh[kh*256*12];
    for (int k=0;k<256;k+=4){
        float4 s = *(const float4*)&Srow[k];
        #pragma unroll
        for (int j=0;j<3;j++)
            acc[j] += s.x*yp[(k+0)*12+g+j] + s.y*yp[(k+1)*12+g+j]
                    + s.z*yp[(k+2)*12+g+j] + s.w*yp[(k+3)*12+g+j];
    }
    #pragma unroll
    for (int j=0;j<3;j++) acc[j] += __shfl_xor_sync(0xffffffffu, acc[j], 4);
    if (kh == 0) {
        #pragma unroll
        for (int j=0;j<3;j++) {
            int t = g + j;
            if (z == 0) g_yf1[((size_t)b*NN + row)*12 + t] = acc[j];
            else        g_yf2[((size_t)b*NN + row)*12 + t] =
                            2.f*acc[j] - ycov[((size_t)b*TT+t)*NN + row];
        }
    }
}

// ---------------- fused cell-phase kernel (round-10 base, folded Y2) ---------
__global__ void __launch_bounds__(256) k_cell(
    int phase, int deFlag, int t,
    const float* __restrict__ x, const float* __restrict__ ycov,
    const float* __restrict__ bias,
    const float* __restrict__ pW, const float* __restrict__ pb,
    float* __restrict__ out)
{
    extern __shared__ char smx[];
    __half* PAN = (__half*)(smx + OFF_PAN);
    __half* SS  = (__half*)(smx + OFF_SS);
    __half* S2S = (__half*)(smx + OFF_S2);
    __half* XB  = (__half*)(smx + OFF_XB);
    float*  GOs = (float*)(smx + OFF_GO);
    __shared__ float pr[2][128];

    const int b  = blockIdx.y;
    const int m0 = blockIdx.x*128;
    const int tid = threadIdx.x;
    const int warp = tid >> 5, lane = tid & 31;
    const int mw = warp & 3, nw = warp >> 2;
    const int tq = lane >> 2, tr = lane & 3;

    const int l8 = lane & 7, mt = lane >> 3;
    const int arow = l8 + (mt & 1)*8;
    const int acol = (mt >> 1)*8;
    const int brow = l8 + (mt >> 1)*8;
    const int bcol = (mt & 1)*8;
    const unsigned aOff0 = ((mw*32 + arow)*24 + acol)*2;
    const unsigned aOff1 = aOff0 + 16*48;
    const unsigned bOff0 = ((nw*32 + brow)*24 + bcol)*2;
    const unsigned bOff1 = bOff0 + 16*48;
    const unsigned uPAN = (unsigned)__cvta_generic_to_shared(PAN);
    const unsigned uSS  = (unsigned)__cvta_generic_to_shared(SS);
    const unsigned uS2  = (unsigned)__cvta_generic_to_shared(S2S);
    const unsigned uXB  = (unsigned)__cvta_generic_to_shared(XB);

    const __half* Sh  = deFlag ? g_sup_de_h + (size_t)b*NN*NN : g_sup_en_h;
    const __half* S2h = deFlag ? g_s2_de_h  + (size_t)b*NN*NN : g_s2_en_h;
    const __half* Xrow = (phase == 0) ? g_x0 : g_x1;
    const __half* XT   = (phase == 0) ? g_x0T : g_x1T;

    // ---- preload panel tiles 0..3 (X own rows) ----
    #pragma unroll
    for (int i = 0; i < 4; i++) {
        int ch = tid + i*256;
        int tI = ch >> 8, rw = (ch >> 1) & 127, off = (ch & 1)*8;
        cpa16(&PAN[tI*TILEH + rw*24 + off],
              &Xrow[((size_t)b*NN + m0 + rw)*64 + tI*16 + off]);
    }
    if (deFlag) {
        GOs[tid]       = g_go[(size_t)b*NN + tid];
        GOs[tid + 256] = g_go[(size_t)b*NN + tid + 256];
    }
    CP_COMMIT();

    // ---- phase A: Y1 = S@X, Y2 = S2@X (K=512) ----
    const int lrA = tid >> 1, loA = (tid & 1)*8;

    float acc1[2][4][4] = {};
    float acc2[2][4][4] = {};
    float d1 = 0.f, d2 = 0.f;
    const int mvrow = tid >> 1, mvh = (tid & 1)*8;

#define PA_LOAD(st, k0) do { \
    cpa16(&SS [(st)*TILEH + lrA*24 + loA], &Sh [(size_t)(m0+lrA)*NN + (k0)+loA]); \
    cpa16(&S2S[(st)*TILEH + lrA*24 + loA], &S2h[(size_t)(m0+lrA)*NN + (k0)+loA]); \
    if (tid < 128) \
        cpa16(&XB[(st)*1536 + lrA*24 + loA], &XT[((size_t)b*64 + lrA)*NN + (k0)+loA]); \
} while(0)

    PA_LOAD(0, 0);  CP_COMMIT();
    PA_LOAD(1, 16); CP_COMMIT();
    for (int kt = 0; kt < 32; kt++) {
        CP_WAIT1();
        __syncthreads();
        if (kt < 30) PA_LOAD((kt+2)%3, (kt+2)*16);
        CP_COMMIT();
        const unsigned sb  = uSS + (kt%3)*TILEB;
        const unsigned s2b = uS2 + (kt%3)*TILEB;
        const unsigned xb  = uXB + (kt%3)*3072;
        unsigned a[2][4], a2[2][4], bb[4][2];
        ldsm_x4(a [0][0], a [0][1], a [0][2], a [0][3], sb  + aOff0);
        ldsm_x4(a [1][0], a [1][1], a [1][2], a [1][3], sb  + aOff1);
        ldsm_x4(a2[0][0], a2[0][1], a2[0][2], a2[0][3], s2b + aOff0);
        ldsm_x4(a2[1][0], a2[1][1], a2[1][2], a2[1][3], s2b + aOff1);
        ldsm_x4(bb[0][0], bb[0][1], bb[1][0], bb[1][1], xb + bOff0);
        ldsm_x4(bb[2][0], bb[2][1], bb[3][0], bb[3][1], xb + bOff1);
        #pragma unroll
        for (int mi = 0; mi < 2; mi++)
            #pragma unroll
            for (int nj = 0; nj < 4; nj++) {
                mma_f16(acc1[mi][nj], a [mi][0], a [mi][1], a [mi][2], a [mi][3],
                        bb[nj][0], bb[nj][1]);
                mma_f16(acc2[mi][nj], a2[mi][0], a2[mi][1], a2[mi][2], a2[mi][3],
                        bb[nj][0], bb[nj][1]);
            }
        if (deFlag) {
            const __half* Ab  = SS  + (kt%3)*TILEH;
            const __half* A2b = S2S + (kt%3)*TILEH;
            const __half2* ap  = (const __half2*)&Ab [mvrow*24 + mvh];
            const __half2* a2p = (const __half2*)&A2b[mvrow*24 + mvh];
            const float* gop = &GOs[kt*16 + mvh];
            #pragma unroll
            for (int j = 0; j < 4; j++) {
                float2 v  = __half22float2(ap[j]);
                float2 v2 = __half22float2(a2p[j]);
                d1 += v.x*gop[2*j] + v.y*gop[2*j+1];
                d2 += v2.x*gop[2*j] + v2.y*gop[2*j+1];
            }
        }
    }
    CP_WAIT0();
    __syncthreads();

    // ---- write Y1 (tiles 4..7), Y2 = S2@X raw (tiles 8..11, folded W) ----
    #pragma unroll
    for (int mi = 0; mi < 2; mi++) {
        int r = mw*32 + mi*16 + tq;
        #pragma unroll
        for (int nj = 0; nj < 4; nj++) {
            int c = nw*32 + nj*8 + tr*2;
            int tI = c >> 4, kk = c & 15;
            #pragma unroll
            for (int hh = 0; hh < 2; hh++) {
                int rr = r + hh*8;
                *(__half2*)&PAN[(4+tI)*TILEH + rr*24 + kk] =
                    __floats2half2_rn(acc1[mi][nj][hh*2], acc1[mi][nj][hh*2+1]);
                *(__half2*)&PAN[(8+tI)*TILEH + rr*24 + kk] =
                    __floats2half2_rn(acc2[mi][nj][hh*2], acc2[mi][nj][hh*2+1]);
            }
        }
    }

    // ---- tile 12: extra features ----
    if (deFlag) {
        d1 += __shfl_xor_sync(0xffffffffu, d1, 1);
        d2 += __shfl_xor_sync(0xffffffffu, d2, 1);
        if ((tid & 1) == 0) {
            int rw = tid >> 1;
            size_t gr = (size_t)b*NN + m0 + rw;
            float go = GOs[m0 + rw];
            __half* T = &PAN[12*TILEH + rw*24];
            T[0] = __float2half(go);
            T[1] = __float2half(ycov[((size_t)b*TT + t)*NN + m0 + rw]);
            T[2] = __float2half(d1);
            T[3] = __float2half(g_yf1[gr*12 + t]);
            T[4] = __float2half(2.f*d2 - go);
            T[5] = __float2half(g_yf2[gr*12 + t]);
            #pragma unroll
            for (int j = 6; j < 16; j++) T[j] = __float2half(0.f);
        }
    } else {
        if (tid < 128) {
            int rw = tid;
            size_t gr = (size_t)b*NN + m0 + rw;
            const float* xp = &x[(((size_t)b*TT + t)*NN + m0 + rw)*2];
            __half* T = &PAN[12*TILEH + rw*24];
            T[0] = __float2half(xp[0]);
            T[1] = __float2half(xp[1]);
            T[2] = __float2half(g_xf1[gr*24 + t*2 + 0]);
            T[3] = __float2half(g_xf1[gr*24 + t*2 + 1]);
            T[4] = __float2half(g_xf2[gr*24 + t*2 + 0]);
            T[5] = __float2half(g_xf2[gr*24 + t*2 + 1]);
            #pragma unroll
            for (int j = 6; j < 16; j++) T[j] = __float2half(0.f);
        }
    }
    __syncthreads();

    // ---- phase B: weight GEMM over K=208 from the panel ----
    if (phase == 0) {
        const __half* WT = deFlag ? g_WgdT : g_WgeT;
        float acc[2][8][4] = {};
        const unsigned bG0 = ((nw*64 + brow)*24 + bcol)*2;
#define WB_LOAD128(st, k0) do { \
    int n_ = tid >> 1, of_ = (tid & 1)*8; \
    cpa16(&SS[(st)*TILEH + n_*24 + of_], &WT[(size_t)n_*208 + (k0)+of_]); \
} while(0)
        WB_LOAD128(0, 0);  CP_COMMIT();
        WB_LOAD128(1, 16); CP_COMMIT();
        for (int kt = 0; kt < 13; kt++) {
            CP_WAIT1();
            __syncthreads();
            if (kt < 11) WB_LOAD128((kt+2)%3, (kt+2)*16);
            CP_COMMIT();
            const unsigned pb_ = uPAN + kt*TILEB;
            const unsigned wb  = uSS + (kt%3)*TILEB;
            unsigned a[2][4], bb[8][2];
            ldsm_x4(a[0][0], a[0][1], a[0][2], a[0][3], pb_ + aOff0);
            ldsm_x4(a[1][0], a[1][1], a[1][2], a[1][3], pb_ + aOff1);
            #pragma unroll
            for (int j = 0; j < 4; j++)
                ldsm_x4(bb[2*j][0], bb[2*j][1], bb[2*j+1][0], bb[2*j+1][1],
                        wb + bG0 + j*16*48);
            #pragma unroll
            for (int mi = 0; mi < 2; mi++)
                #pragma unroll
                for (int nj = 0; nj < 8; nj++)
                    mma_f16(acc[mi][nj], a[mi][0], a[mi][1], a[mi][2], a[mi][3],
                            bb[nj][0], bb[nj][1]);
        }
        // epilogue: z = sigmoid -> z*h into g_x1/g_x1T ; r into g_r
        #pragma unroll
        for (int mi = 0; mi < 2; mi++) {
            int r0 = mw*32 + mi*16 + tq;
            #pragma unroll
            for (int nj = 0; nj < 8; nj++) {
                int c = nw*64 + nj*8 + tr*2;
                #pragma unroll
                for (int hh = 0; hh < 2; hh++) {
                    int ln = m0 + r0 + hh*8;
                    size_t row = (size_t)b*NN + ln;
                    float va = acc[mi][nj][hh*2], vb = acc[mi][nj][hh*2+1];
                    float za = 1.f/(1.f + expf(-(va + bias[c])));
                    float zb = 1.f/(1.f + expf(-(vb + bias[c+1])));
                    if (c < 64) {
                        float ha = za * g_h[row*HID + c];
                        float hb = zb * g_h[row*HID + c+1];
                        *(__half2*)&g_x1[row*64 + c] = __floats2half2_rn(ha, hb);
                        g_x1T[((size_t)b*64 + c  )*NN + ln] = __float2half(ha);
                        g_x1T[((size_t)b*64 + c+1)*NN + ln] = __float2half(hb);
                    } else {
                        g_r[row*HID + (c-64)]   = za;
                        g_r[row*HID + (c-64)+1] = zb;
                    }
                }
            }
        }
#undef WB_LOAD128
    } else {
        const __half* WT = deFlag ? g_WudT : g_WueT;
        float acc[2][4][4] = {};
#define WB_LOAD64(st, k0) do { \
    if (tid < 128) { int n_ = tid >> 1, of_ = (tid & 1)*8; \
        cpa16(&SS[(st)*1536 + n_*24 + of_], &WT[(size_t)n_*208 + (k0)+of_]); } \
} while(0)
        WB_LOAD64(0, 0);  CP_COMMIT();
        WB_LOAD64(1, 16); CP_COMMIT();
        for (int kt = 0; kt < 13; kt++) {
            CP_WAIT1();
            __syncthreads();
            if (kt < 11) WB_LOAD64((kt+2)%3, (kt+2)*16);
            CP_COMMIT();
            const unsigned pb_ = uPAN + kt*TILEB;
            const unsigned wb  = uSS + (kt%3)*3072;
            unsigned a[2][4], bb[4][2];
            ldsm_x4(a[0][0], a[0][1], a[0][2], a[0][3], pb_ + aOff0);
            ldsm_x4(a[1][0], a[1][1], a[1][2], a[1][3], pb_ + aOff1);
            ldsm_x4(bb[0][0], bb[0][1], bb[1][0], bb[1][1], wb + bOff0);
            ldsm_x4(bb[2][0], bb[2][1], bb[3][0], bb[3][1], wb + bOff1);
            #pragma unroll
            for (int mi = 0; mi < 2; mi++)
                #pragma unroll
                for (int nj = 0; nj < 4; nj++)
                    mma_f16(acc[mi][nj], a[mi][0], a[mi][1], a[mi][2], a[mi][3],
                            bb[nj][0], bb[nj][1]);
        }
        // epilogue: h update (+ projection for decoder)
        const bool doProj = (deFlag != 0);
        float rowsum[2][2] = {};
        #pragma unroll
        for (int mi = 0; mi < 2; mi++) {
            int r0 = mw*32 + mi*16 + tq;
            #pragma unroll
            for (int nj = 0; nj < 4; nj++) {
                int c = nw*32 + nj*8 + tr*2;
                #pragma unroll
                for (int hh = 0; hh < 2; hh++) {
                    int ln = m0 + r0 + hh*8;
                    size_t row = (size_t)b*NN + ln;
                    float hn2[2];
                    #pragma unroll
                    for (int jj = 0; jj < 2; jj++) {
                        int o = c + jj;
                        float hc = tanhf(acc[mi][nj][hh*2+jj] + bias[o]);
                        float r  = g_r[row*HID + o];
                        float h  = g_h[row*HID + o];
                        float hn = r*h + (1.f - r)*hc;
                        g_h[row*HID + o] = hn;
                        g_x0T[((size_t)b*64 + o)*NN + ln] = __float2half(hn);
                        hn2[jj] = hn;
                        if (doProj) rowsum[mi][hh] += hn * pW[o];
                    }
                    *(__half2*)&g_x0[row*64 + c] = __floats2half2_rn(hn2[0], hn2[1]);
                }
            }
        }
        if (doProj) {
            #pragma unroll
            for (int mi = 0; mi < 2; mi++)
                #pragma unroll
                for (int hh = 0; hh < 2; hh++) {
                    float v = rowsum[mi][hh];
                    v += __shfl_xor_sync(0xffffffffu, v, 1);
                    v += __shfl_xor_sync(0xffffffffu, v, 2);
                    if (tr == 0) pr[nw][mw*32 + mi*16 + tq + hh*8] = v;
                }
            __syncthreads();
            if (tid < 128) {
                int n = m0 + tid;
                float go = pr[0][tid] + pr[1][tid] + pb[0];
                g_go[(size_t)b*NN + n] = go;
                out[((size_t)b*TT + t)*NN + n] = go;
            }
        }
#undef WB_LOAD64
    }
#undef PA_LOAD
}

// ---------------- hyper projection ------------------------------------------
__global__ void k_hyper(const float* __restrict__ hW, const float* __restrict__ hb) {
    int idx = blockIdx.x*blockDim.x + threadIdx.x;
    if (idx >= BN*EMB) return;
    int bn = idx / EMB, e = idx % EMB;
    float s = hb[e];
    #pragma unroll
    for (int k = 0; k < HID; k++) s += g_h[(size_t)bn*HID + k] * hW[k*EMB + e];
    g_ne[idx] = s;
}

// ---------------- orchestration ---------------------------------------------
extern "C" void kernel_launch(void* const* d_in, const int* in_sizes, int n_in,
                              void* d_out, int out_size) {
    const float* x       = (const float*)d_in[0];
    const float* ycov    = (const float*)d_in[1];
    const float* emb     = (const float*)d_in[2];
    const float* enc_gW  = (const float*)d_in[3];
    const float* enc_gb  = (const float*)d_in[4];
    const float* enc_uW  = (const float*)d_in[5];
    const float* enc_ub  = (const float*)d_in[6];
    const float* dec_gW  = (const float*)d_in[7];
    const float* dec_gb  = (const float*)d_in[8];
    const float* dec_uW  = (const float*)d_in[9];
    const float* dec_ub  = (const float*)d_in[10];
    const float* proj_W  = (const float*)d_in[11];
    const float* proj_b  = (const float*)d_in[12];
    const float* hyper_W = (const float*)d_in[13];
    const float* hyper_b = (const float*)d_in[14];
    float* out = (float*)d_out;

    static int smem_set = 0;
    if (!smem_set) {
        cudaFuncSetAttribute(k_cell, cudaFuncAttributeMaxDynamicSharedMemorySize,
                             SM_BYTES);
        smem_set = 1;
    }

    dim3 gs_cell(4, BB);
    dim3 gs_tr_en(8, 8, 1);
    dim3 gs_tr_de(8, 8, BB);
    dim3 gs_sq_en(4, 8, 1);
    dim3 gs_sq_de(4, 8, BB);
    dim3 gs_pre(16, BB, 2);

    k_zero<<<1024, 256>>>();
    k_prep<<<(208*128+255)/256, 256>>>(enc_gW, 0);
    k_prep<<<(208*128+255)/256, 256>>>(dec_gW, 1);
    k_prep<<<(208*64+255)/256, 256>>>(enc_uW, 2);
    k_prep<<<(208*64+255)/256, 256>>>(dec_uW, 3);
    k_support_en<<<NN, 256>>>(emb);
    k_tr<<<gs_tr_en, 256>>>(0);
    k_sq<<<gs_sq_en, 256>>>(0);
    k_pre_enc<<<gs_pre, 256>>>(x);

    for (int t = 0; t < TT; t++) {
        k_cell<<<gs_cell, 256, SM_BYTES>>>(0, 0, t, x, ycov, enc_gb,
                                           nullptr, nullptr, nullptr);
        k_cell<<<gs_cell, 256, SM_BYTES>>>(1, 0, t, x, ycov, enc_ub,
                                           nullptr, nullptr, nullptr);
    }

    k_hyper<<<(BN*EMB + 255)/256, 256>>>(hyper_W, hyper_b);
    k_support_de<<<BN, 256>>>();
    k_tr<<<gs_tr_de, 256>>>(1);
    k_sq<<<gs_sq_de, 256>>>(1);
    k_pre_dec<<<gs_pre, 256>>>(ycov);

    for (int t = 0; t < TT; t++) {
        k_cell<<<gs_cell, 256, SM_BYTES>>>(0, 1, t, x, ycov, dec_gb,
                                           nullptr, nullptr, nullptr);
        k_cell<<<gs_cell, 256, SM_BYTES>>>(1, 1, t, x, ycov, dec_ub,
                                           proj_W, proj_b, out);
    }
}